// round 9
// baseline (speedup 1.0000x reference)
#include <cuda_runtime.h>
#include <cuda_bf16.h>
#include <cstdint>

#define NB   8192
#define NS   100
#define NE   64
#define NH1  128
#define NH2  64
#define NF   128

#define ASTRIDE 272                 // padded bf16 row stride in bytes (128*2 + 16)
#define A_BYTES (128 * ASTRIDE)     // 34816
#define B2_BYTES (64 * ASTRIDE)     // 17408

// ---- smem byte offsets ----
#define OFF_AH    0                    // A hi  (Kp, later H0)
#define OFF_AL    (OFF_AH + A_BYTES)   // A lo
#define OFF_B1H   (OFF_AL + A_BYTES)   // Wcat^T hi [128h][128f]
#define OFF_B1L   (OFF_B1H + A_BYTES)
#define OFF_B2H   (OFF_B1L + A_BYTES)  // W1^T hi [64j][128h]
#define OFF_B2L   (OFF_B2H + B2_BYTES)
#define OFF_C     (OFF_B2L + B2_BYTES) // c[128] f32
#define OFF_Q     (OFF_C + 512)
#define OFF_W2    (OFF_Q + 256)
#define OFF_B1B   (OFF_W2 + 256)
#define OFF_SCORE (OFF_B1B + 256)      // 128 f32
#define OFF_PART  (OFF_SCORE + 512)    // 128*2 f32
#define OFF_POUT  (OFF_PART + 1024)    // 4*64 f32
#define SMEM_TOTAL (OFF_POUT + 1024)   // = 177920 B

// ---- device scratch: pre-split weights, [n][k] bf16, 136-elem row stride ----
__device__ __nv_bfloat16 g_B1[2][128 * 136];
__device__ __nv_bfloat16 g_B2[2][64 * 136];
__device__ float g_Wq[NE * NH1];    // [e][h] = W0a + W0d

// ================= helpers =================
__device__ __forceinline__ uint32_t smem_u32(const void* p) {
    uint32_t a;
    asm("{ .reg .u64 t; cvta.to.shared.u64 t, %1; cvt.u32.u64 %0, t; }" : "=r"(a) : "l"(p));
    return a;
}
__device__ __forceinline__ void ldsm4(uint32_t* r, uint32_t addr) {
    asm volatile("ldmatrix.sync.aligned.m8n8.x4.shared.b16 {%0,%1,%2,%3}, [%4];"
                 : "=r"(r[0]), "=r"(r[1]), "=r"(r[2]), "=r"(r[3]) : "r"(addr));
}
__device__ __forceinline__ void mma_bf16(float* c, const uint32_t* a, uint32_t b0, uint32_t b1) {
    asm volatile("mma.sync.aligned.m16n8k16.row.col.f32.bf16.bf16.f32 "
                 "{%0,%1,%2,%3}, {%4,%5,%6,%7}, {%8,%9}, {%0,%1,%2,%3};"
                 : "+f"(c[0]), "+f"(c[1]), "+f"(c[2]), "+f"(c[3])
                 : "r"(a[0]), "r"(a[1]), "r"(a[2]), "r"(a[3]), "r"(b0), "r"(b1));
}
// pack (lo -> lower half, hi -> upper half)
__device__ __forceinline__ uint32_t cvt_bf16x2(float lo, float hi) {
    uint32_t r;
    asm("cvt.rn.bf16x2.f32 %0, %1, %2;" : "=r"(r) : "f"(hi), "f"(lo));
    return r;
}
__device__ __forceinline__ void split_pair(float x0, float x1, uint32_t& hi2, uint32_t& lo2) {
    hi2 = cvt_bf16x2(x0, x1);
    float h0 = __uint_as_float(hi2 << 16);
    float h1 = __uint_as_float(hi2 & 0xffff0000u);
    lo2 = cvt_bf16x2(x0 - h0, x1 - h1);
}

// ================= prep: fold + split weights =================
__global__ void prep_kernel(const float* __restrict__ W0, const float* __restrict__ W1) {
    int gid = blockIdx.x * blockDim.x + threadIdx.x;
    if (gid < 16384) {                 // B1: n=h, k=f -> Wcat[f][h]
        int n = gid >> 7, k = gid & 127;
        float v;
        if (k < 64) v = W0[(64 + k) * NH1 + n] - W0[(192 + k) * NH1 + n];
        else        v = W0[(128 + (k - 64)) * NH1 + n];
        __nv_bfloat16 h = __float2bfloat16(v);
        g_B1[0][n * 136 + k] = h;
        g_B1[1][n * 136 + k] = __float2bfloat16(v - __bfloat162float(h));
    } else if (gid < 24576) {          // B2: n=j, k=h -> W1[h][j]
        int i = gid - 16384;
        int n = i >> 7, k = i & 127;
        float v = W1[k * NH2 + n];
        __nv_bfloat16 h = __float2bfloat16(v);
        g_B2[0][n * 136 + k] = h;
        g_B2[1][n * 136 + k] = __float2bfloat16(v - __bfloat162float(h));
    } else if (gid < 32768) {          // Wq = W0a + W0d
        int i = gid - 24576;
        int e = i >> 7, hh = i & 127;
        g_Wq[e * NH1 + hh] = W0[e * NH1 + hh] + W0[(192 + e) * NH1 + hh];
    }
}

// ================= fused kernel: 1 CTA = 1 batch, 256 threads =================
__global__ __launch_bounds__(256, 1)
void din_kernel(const float* __restrict__ q_g,
                const float* __restrict__ keys_g,
                const int*   __restrict__ klen_g,
                const float* __restrict__ b0_g,
                const float* __restrict__ b1_g,
                const float* __restrict__ W2_g,
                const float* __restrict__ b2_g,
                float* __restrict__ out_g,
                float* __restrict__ attn_g) {
    extern __shared__ char smem[];
    const uint32_t sbase = smem_u32(smem);
    float* sC     = (float*)(smem + OFF_C);
    float* sQ     = (float*)(smem + OFF_Q);
    float* sW2    = (float*)(smem + OFF_W2);
    float* sB1b   = (float*)(smem + OFF_B1B);
    float* sScore = (float*)(smem + OFF_SCORE);
    float* sPart  = (float*)(smem + OFF_PART);
    float* sPOut  = (float*)(smem + OFF_POUT);

    const int b = blockIdx.x;
    const int t = threadIdx.x;
    const int lane = t & 31, w = t >> 5;
    const int len = klen_g[b];
    const float b2v = b2_g[0];

    // ---- weight tiles -> smem (straight uint4 copies, L2-hot) ----
    {
        const uint4* s1 = (const uint4*)&g_B1[0][0];
        uint4* d1 = (uint4*)(smem + OFF_B1H);
        #pragma unroll 4
        for (int i = t; i < (2 * A_BYTES) / 16; i += 256) d1[i] = s1[i];
        const uint4* s2 = (const uint4*)&g_B2[0][0];
        uint4* d2 = (uint4*)(smem + OFF_B2H);
        #pragma unroll 4
        for (int i = t; i < (2 * B2_BYTES) / 16; i += 256) d2[i] = s2[i];
    }
    if (t < 64) { sQ[t] = q_g[b * NE + t]; sW2[t] = W2_g[t]; sB1b[t] = b1_g[t]; }
    __syncthreads();   // sQ ready for Kp build

    // ---- c[h] = b0[h] + sum_e q[e] * Wq[e][h] ----
    if (t < NH1) {
        float acc = b0_g[t];
        #pragma unroll 8
        for (int e = 0; e < NE; e++) acc = fmaf(sQ[e], g_Wq[e * NH1 + t], acc);
        sC[t] = acc;
    }

    // ---- A1 = [keys | keys*q] bf16 hi/lo into padded smem ----
    for (int i = t; i < NS * 32; i += 256) {
        int s = i >> 5, p = i & 31;           // element pair (2p, 2p+1)
        float2 kv = *(const float2*)&keys_g[((size_t)b * NS + s) * NE + 2 * p];
        uint32_t hi, lo;
        split_pair(kv.x, kv.y, hi, lo);
        *(uint32_t*)(smem + OFF_AH + s * ASTRIDE + p * 4) = hi;
        *(uint32_t*)(smem + OFF_AL + s * ASTRIDE + p * 4) = lo;
        float q0 = sQ[2 * p], q1 = sQ[2 * p + 1];
        split_pair(kv.x * q0, kv.y * q1, hi, lo);
        *(uint32_t*)(smem + OFF_AH + s * ASTRIDE + 128 + p * 4) = hi;
        *(uint32_t*)(smem + OFF_AL + s * ASTRIDE + 128 + p * 4) = lo;
    }
    // zero pad rows 100..127 (both hi and lo)
    for (int i = t; i < 28 * 17 * 2; i += 256) {
        int m = i / (28 * 17), r = (i % (28 * 17)) / 17, cc = i % 17;
        *(uint4*)(smem + (m ? OFF_AL : OFF_AH) + (100 + r) * ASTRIDE + cc * 16) =
            make_uint4(0, 0, 0, 0);
    }
    __syncthreads();

    // ---- lane geometry for ldmatrix ----
    const uint32_t aRow = lane & 15;
    const uint32_t aCol = ((lane >> 4) & 1) * 16;           // bytes
    const uint32_t bRow = (lane & 7) + ((lane >> 4) & 1) * 8;
    const uint32_t bCol = ((lane >> 3) & 1) * 16;           // bytes

    const int mg = w >> 1, s0 = mg * 32;
    const uint32_t aBaseH0 = sbase + OFF_AH + (s0 + aRow) * ASTRIDE + aCol;
    const uint32_t aBaseH1 = aBaseH0 + 16 * ASTRIDE;
    const uint32_t aBaseL0 = aBaseH0 + A_BYTES;
    const uint32_t aBaseL1 = aBaseH1 + A_BYTES;

    // ================= GEMM1: D1[128s x 128h] = Kp @ Wcat =================
    float acc[16][4];
    {
        const int ng = w & 1, h0 = ng * 64;
        #pragma unroll
        for (int i = 0; i < 16; i++)
            #pragma unroll
            for (int j = 0; j < 4; j++) acc[i][j] = 0.f;

        uint32_t bBaseH[4], bBaseL[4];
        #pragma unroll
        for (int np = 0; np < 4; np++) {
            bBaseH[np] = sbase + OFF_B1H + (h0 + np * 16 + bRow) * ASTRIDE + bCol;
            bBaseL[np] = bBaseH[np] + A_BYTES;
        }

        #pragma unroll
        for (int k = 0; k < 8; k++) {
            const uint32_t ko = k * 32;
            uint32_t ah0[4], ah1[4], al0[4], al1[4];
            ldsm4(ah0, aBaseH0 + ko);
            ldsm4(ah1, aBaseH1 + ko);
            ldsm4(al0, aBaseL0 + ko);
            ldsm4(al1, aBaseL1 + ko);
            uint32_t bh[4][4], bl[4][4];
            #pragma unroll
            for (int np = 0; np < 4; np++) {
                ldsm4(bh[np], bBaseH[np] + ko);
                ldsm4(bl[np], bBaseL[np] + ko);
            }
            #pragma unroll
            for (int np = 0; np < 4; np++) {
                #pragma unroll
                for (int half = 0; half < 2; half++) {
                    const int nt = np * 2 + half;
                    const uint32_t bh0 = bh[np][half * 2], bh1 = bh[np][half * 2 + 1];
                    const uint32_t bl0 = bl[np][half * 2], bl1 = bl[np][half * 2 + 1];
                    mma_bf16(acc[nt],     ah0, bh0, bh1);
                    mma_bf16(acc[nt],     ah0, bl0, bl1);
                    mma_bf16(acc[nt],     al0, bh0, bh1);
                    mma_bf16(acc[8 + nt], ah1, bh0, bh1);
                    mma_bf16(acc[8 + nt], ah1, bl0, bl1);
                    mma_bf16(acc[8 + nt], al1, bh0, bh1);
                }
            }
        }
    }
    __syncthreads();   // done reading A1

    // ---- epilogue1: H0 = relu(D1 + c) -> split bf16 -> A region ----
    {
        const int ng = w & 1, h0 = ng * 64;
        #pragma unroll
        for (int mt = 0; mt < 2; mt++) {
            #pragma unroll
            for (int nt = 0; nt < 8; nt++) {
                const float* c = acc[mt * 8 + nt];
                const int row = s0 + mt * 16 + (lane >> 2);
                const int col = h0 + nt * 8 + (lane & 3) * 2;
                const float c0 = sC[col], c1 = sC[col + 1];
                uint32_t hi, lo;
                split_pair(fmaxf(c[0] + c0, 0.f), fmaxf(c[1] + c1, 0.f), hi, lo);
                *(uint32_t*)(smem + OFF_AH + row * ASTRIDE + col * 2) = hi;
                *(uint32_t*)(smem + OFF_AL + row * ASTRIDE + col * 2) = lo;
                split_pair(fmaxf(c[2] + c0, 0.f), fmaxf(c[3] + c1, 0.f), hi, lo);
                *(uint32_t*)(smem + OFF_AH + (row + 8) * ASTRIDE + col * 2) = hi;
                *(uint32_t*)(smem + OFF_AL + (row + 8) * ASTRIDE + col * 2) = lo;
            }
        }
    }
    __syncthreads();

    // ================= GEMM2: D2[128s x 64j] = H0 @ W1 =================
    float acc2[8][4];
    const int ng2 = w & 1, j0 = ng2 * 32;
    {
        #pragma unroll
        for (int i = 0; i < 8; i++)
            #pragma unroll
            for (int j = 0; j < 4; j++) acc2[i][j] = 0.f;

        uint32_t bBaseH[2], bBaseL[2];
        #pragma unroll
        for (int np = 0; np < 2; np++) {
            bBaseH[np] = sbase + OFF_B2H + (j0 + np * 16 + bRow) * ASTRIDE + bCol;
            bBaseL[np] = bBaseH[np] + B2_BYTES;
        }

        #pragma unroll
        for (int k = 0; k < 8; k++) {
            const uint32_t ko = k * 32;
            uint32_t ah0[4], ah1[4], al0[4], al1[4];
            ldsm4(ah0, aBaseH0 + ko);
            ldsm4(ah1, aBaseH1 + ko);
            ldsm4(al0, aBaseL0 + ko);
            ldsm4(al1, aBaseL1 + ko);
            uint32_t bh[2][4], bl[2][4];
            #pragma unroll
            for (int np = 0; np < 2; np++) {
                ldsm4(bh[np], bBaseH[np] + ko);
                ldsm4(bl[np], bBaseL[np] + ko);
            }
            #pragma unroll
            for (int np = 0; np < 2; np++) {
                #pragma unroll
                for (int half = 0; half < 2; half++) {
                    const int nt = np * 2 + half;
                    const uint32_t bh0 = bh[np][half * 2], bh1 = bh[np][half * 2 + 1];
                    const uint32_t bl0 = bl[np][half * 2], bl1 = bl[np][half * 2 + 1];
                    mma_bf16(acc2[nt],     ah0, bh0, bh1);
                    mma_bf16(acc2[nt],     ah0, bl0, bl1);
                    mma_bf16(acc2[nt],     al0, bh0, bh1);
                    mma_bf16(acc2[4 + nt], ah1, bh0, bh1);
                    mma_bf16(acc2[4 + nt], ah1, bl0, bl1);
                    mma_bf16(acc2[4 + nt], al1, bh0, bh1);
                }
            }
        }
    }

    // ---- epilogue2: scores = sum_j relu(D2 + b1)*W2 ----
    {
        float part[4] = {0.f, 0.f, 0.f, 0.f};   // [mt][rowhalf]
        #pragma unroll
        for (int mt = 0; mt < 2; mt++) {
            #pragma unroll
            for (int nt = 0; nt < 4; nt++) {
                const float* c = acc2[mt * 4 + nt];
                const int col = j0 + nt * 8 + (lane & 3) * 2;
                const float bb0 = sB1b[col], bb1 = sB1b[col + 1];
                const float w0v = sW2[col],  w1v = sW2[col + 1];
                part[mt * 2]     += fmaxf(c[0] + bb0, 0.f) * w0v + fmaxf(c[1] + bb1, 0.f) * w1v;
                part[mt * 2 + 1] += fmaxf(c[2] + bb0, 0.f) * w0v + fmaxf(c[3] + bb1, 0.f) * w1v;
            }
        }
        #pragma unroll
        for (int i = 0; i < 4; i++) {
            float v = part[i];
            v += __shfl_xor_sync(0xffffffffu, v, 1);
            v += __shfl_xor_sync(0xffffffffu, v, 2);
            if ((lane & 3) == 0) {
                const int row = s0 + (i >> 1) * 16 + (lane >> 2) + (i & 1) * 8;
                sPart[row * 2 + ng2] = v;
            }
        }
    }
    __syncthreads();
    if (t < 128) sScore[t] = sPart[t * 2] + sPart[t * 2 + 1] + b2v;
    __syncthreads();

    // ---- masked softmax (warp 0) ----
    if (t < 32) {
        float m = -1e30f;
        for (int s = t; s < NS; s += 32) {
            float v = (s < len) ? sScore[s] : -1e30f;
            m = fmaxf(m, v);
        }
        #pragma unroll
        for (int off = 16; off; off >>= 1) m = fmaxf(m, __shfl_xor_sync(0xffffffffu, m, off));
        float sum = 0.f;
        for (int s = t; s < NS; s += 32) {
            float v = (s < len) ? expf(sScore[s] - m) : 0.f;
            sScore[s] = v;
            sum += v;
        }
        #pragma unroll
        for (int off = 16; off; off >>= 1) sum += __shfl_xor_sync(0xffffffffu, sum, off);
        float inv = 1.f / sum;
        for (int s = t; s < NS; s += 32) sScore[s] *= inv;
    }
    __syncthreads();

    // ---- out[e] = sum_s attn[s] * keys[s][e] (keys L2-hot) ----
    {
        const int e = t & 63, g = t >> 6;
        const float* kb = keys_g + (size_t)b * NS * NE;
        float a = 0.f;
        for (int s = g; s < NS; s += 4) a = fmaf(sScore[s], kb[s * NE + e], a);
        sPOut[g * 64 + e] = a;
    }
    __syncthreads();
    if (t < 64)
        out_g[(size_t)b * NE + t] = sPOut[t] + sPOut[64 + t] + sPOut[128 + t] + sPOut[192 + t];
    if (attn_g && t < NS) attn_g[(size_t)b * NS + t] = sScore[t];
}

extern "C" void kernel_launch(void* const* d_in, const int* in_sizes, int n_in,
                              void* d_out, int out_size) {
    const float* query = (const float*)d_in[0];
    const float* keys  = (const float*)d_in[1];
    const int*   klen  = (const int*)  d_in[2];
    const float* W0    = (const float*)d_in[3];
    const float* b0    = (const float*)d_in[4];
    const float* W1    = (const float*)d_in[5];
    const float* b1    = (const float*)d_in[6];
    const float* W2    = (const float*)d_in[7];
    const float* b2    = (const float*)d_in[8];

    float* outp  = (float*)d_out;
    float* attnp = (out_size >= NB * NE + NB * NS) ? outp + (size_t)NB * NE : nullptr;

    cudaFuncSetAttribute(din_kernel, cudaFuncAttributeMaxDynamicSharedMemorySize, SMEM_TOTAL);

    prep_kernel<<<64, 512>>>(W0, W1);
    din_kernel<<<NB, 256, SMEM_TOTAL>>>(query, keys, klen, b0, b1, W2, b2, outp, attnp);
}

// round 10
// speedup vs baseline: 1.6964x; 1.6964x over previous
#include <cuda_runtime.h>
#include <cuda_bf16.h>
#include <cstdint>

#define NB   8192
#define NS   100
#define NE   64
#define NH1  128
#define NH2  64

// ---- smem layout (bytes) ----
#define OFF_A     0                      // A hi [256rows x 128k] swizzled (65536) + lo (65536)
#define A_HALF    65536
#define OFF_B1    131072                 // B1 hi (32768) + lo (32768)
#define B1_HALF   32768
#define OFF_B2    196608                 // B2 hi (16384) + lo (16384)
#define B2_HALF   16384
#define OFF_SQ    229376                 // q[2][64] f32 (512)
#define OFF_W2    229888                 // W2[64] (256)
#define OFF_B1B   230144                 // b1[64] (256)
#define OFF_SCORE 230400                 // scores[2][128] f32 (1024); overlaid: c[2][128]
#define SMEM_TOTAL 231424
// overlays inside A region (valid only after GEMM2):
#define OFF_PART  (OFF_A)                // [256][2] f32 = 2048
#define OFF_POUT  (OFF_A + 4096)         // [2][4][64] f32 = 2048

// ---- device scratch: pre-split, pre-swizzled weights ----
__device__ uint4 g_B1[2][2048];   // hi/lo 32KB each, [128n][128k] swizzled nar=16
__device__ uint4 g_B2[2][1024];   // hi/lo 16KB each, [64n][128k]  swizzled nar=8
__device__ float g_Wq[NE * NH1];  // [e][h] = W0a + W0d

// ================= helpers =================
__device__ __forceinline__ uint32_t smem_u32(const void* p) {
    uint32_t a;
    asm("{ .reg .u64 t; cvta.to.shared.u64 t, %1; cvt.u32.u64 %0, t; }" : "=r"(a) : "l"(p));
    return a;
}
__device__ __forceinline__ void ldsm4(uint32_t* r, uint32_t addr) {
    asm volatile("ldmatrix.sync.aligned.m8n8.x4.shared.b16 {%0,%1,%2,%3}, [%4];"
                 : "=r"(r[0]), "=r"(r[1]), "=r"(r[2]), "=r"(r[3]) : "r"(addr));
}
__device__ __forceinline__ void mma_bf16(float* c, const uint32_t* a, uint32_t b0, uint32_t b1) {
    asm volatile("mma.sync.aligned.m16n8k16.row.col.f32.bf16.bf16.f32 "
                 "{%0,%1,%2,%3}, {%4,%5,%6,%7}, {%8,%9}, {%0,%1,%2,%3};"
                 : "+f"(c[0]), "+f"(c[1]), "+f"(c[2]), "+f"(c[3])
                 : "r"(a[0]), "r"(a[1]), "r"(a[2]), "r"(a[3]), "r"(b0), "r"(b1));
}
__device__ __forceinline__ uint32_t cvt_bf16x2(float lo, float hi) {
    uint32_t r;
    asm("cvt.rn.bf16x2.f32 %0, %1, %2;" : "=r"(r) : "f"(hi), "f"(lo));
    return r;
}
__device__ __forceinline__ void split_pair(float x0, float x1, uint32_t& hi2, uint32_t& lo2) {
    hi2 = cvt_bf16x2(x0, x1);
    float h0 = __uint_as_float(hi2 << 16);
    float h1 = __uint_as_float(hi2 & 0xffff0000u);
    lo2 = cvt_bf16x2(x0 - h0, x1 - h1);
}
// swizzled byte offset inside A (256 rows, nar=32): row 0..255, k elem 0..127
__device__ __forceinline__ uint32_t boffA(int row, int k) {
    return (uint32_t)((((row >> 3) + (k >> 6) * 32) << 10) + ((row & 7) << 7)
                      + ((((k & 63) << 1)) ^ ((row & 7) << 4)));
}
// generic swizzled offset for prep (nar = rows/8)
__device__ __forceinline__ uint32_t boffB(int n, int k, int nar) {
    return (uint32_t)((((n >> 3) + (k >> 6) * nar) << 10) + ((n & 7) << 7)
                      + ((((k & 63) << 1)) ^ ((n & 7) << 4)));
}

// ================= prep: fold + split + swizzle weights =================
__global__ void prep_kernel(const float* __restrict__ W0, const float* __restrict__ W1) {
    int gid = blockIdx.x * blockDim.x + threadIdx.x;
    if (gid < 16384) {                 // B1: n=h, k=f -> Wcat[f][h]
        int n = gid >> 7, k = gid & 127;
        float v;
        if (k < 64) v = W0[(64 + k) * NH1 + n] - W0[(192 + k) * NH1 + n];
        else        v = W0[(128 + (k - 64)) * NH1 + n];
        __nv_bfloat16 h = __float2bfloat16(v);
        uint32_t off = boffB(n, k, 16);
        *(__nv_bfloat16*)((char*)&g_B1[0][0] + off) = h;
        *(__nv_bfloat16*)((char*)&g_B1[1][0] + off) =
            __float2bfloat16(v - __bfloat162float(h));
    } else if (gid < 24576) {          // B2: n=j, k=h -> W1[h][j]
        int i = gid - 16384;
        int n = i >> 7, k = i & 127;
        float v = W1[k * NH2 + n];
        __nv_bfloat16 h = __float2bfloat16(v);
        uint32_t off = boffB(n, k, 8);
        *(__nv_bfloat16*)((char*)&g_B2[0][0] + off) = h;
        *(__nv_bfloat16*)((char*)&g_B2[1][0] + off) =
            __float2bfloat16(v - __bfloat162float(h));
    } else if (gid < 32768) {          // Wq = W0a + W0d
        int i = gid - 24576;
        int e = i >> 7, hh = i & 127;
        g_Wq[e * NH1 + hh] = W0[e * NH1 + hh] + W0[(192 + e) * NH1 + hh];
    }
}

// ================= persistent fused kernel: 512 threads, 2 batches/iter =================
__global__ __launch_bounds__(512, 1)
void din_kernel(const float* __restrict__ q_g,
                const float* __restrict__ keys_g,
                const int*   __restrict__ klen_g,
                const float* __restrict__ b0_g,
                const float* __restrict__ b1_g,
                const float* __restrict__ W2_g,
                const float* __restrict__ b2_g,
                float* __restrict__ out_g,
                float* __restrict__ attn_g,
                int npairs) {
    extern __shared__ char smem[];
    const uint32_t sbase = smem_u32(smem);
    float* sQ     = (float*)(smem + OFF_SQ);
    float* sW2    = (float*)(smem + OFF_W2);
    float* sB1b   = (float*)(smem + OFF_B1B);
    float* sScore = (float*)(smem + OFF_SCORE);   // also c[] (disjoint phases)
    float* sPart  = (float*)(smem + OFF_PART);
    float* sPOut  = (float*)(smem + OFF_POUT);

    const int t = threadIdx.x;
    const int lane = t & 31, w = t >> 5;
    const float b2v = b2_g[0];

    // ---- weights -> smem ONCE ----
    {
        const uint4* s1 = &g_B1[0][0];
        uint4* d1 = (uint4*)(smem + OFF_B1);
        #pragma unroll 4
        for (int i = t; i < 4096; i += 512) d1[i] = s1[i];
        const uint4* s2 = &g_B2[0][0];
        uint4* d2 = (uint4*)(smem + OFF_B2);
        #pragma unroll 4
        for (int i = t; i < 2048; i += 512) d2[i] = s2[i];
        if (t < 64) { sW2[t] = W2_g[t]; sB1b[t] = b1_g[t]; }
    }

    // ---- lane geometry (constants across iterations) ----
    const int mg = w >> 1, ng = w & 1;
    const int s0 = mg * 32;                      // warp row base (0..224)
    const int batchw = mg >> 2;                  // warp's batch within pair
    const int rA = s0 + (lane & 15);
    const uint32_t aBase = sbase + OFF_A + ((rA >> 3) << 10) + ((rA & 7) << 7);
    const uint32_t hsxA = (((lane >> 4) & 1) * 16) ^ ((lane & 7) << 4);
    const uint32_t hsxB = (((lane >> 3) & 1) * 16) ^ ((lane & 7) << 4);
    const int h0 = ng * 64, j0 = ng * 32;
    const uint32_t b1Base = sbase + OFF_B1 + (((h0 >> 3) + ((lane >> 4) & 1)) << 10)
                          + ((lane & 7) << 7);
    const uint32_t b2Base = sbase + OFF_B2 + (((j0 >> 3) + ((lane >> 4) & 1)) << 10)
                          + ((lane & 7) << 7);

    for (int p = blockIdx.x; p < npairs; p += gridDim.x) {
        const long gb0 = (long)p * 2;

        // ---- per-pair q ----
        if (t < 128) sQ[t] = q_g[(gb0 + (t >> 6)) * NE + (t & 63)];
        __syncthreads();

        // ---- build Kp (2 batches) into A hi/lo ----
        for (int i = t; i < 6400; i += 512) {
            int batch = i / 3200, rem = i - batch * 3200;
            int s = rem >> 5, pp = rem & 31;
            int row = batch * 128 + s;
            float2 kv = *(const float2*)&keys_g[((gb0 + batch) * NS + s) * NE + 2 * pp];
            uint32_t hi, lo;
            split_pair(kv.x, kv.y, hi, lo);
            uint32_t o = boffA(row, 2 * pp);
            *(uint32_t*)(smem + OFF_A + o) = hi;
            *(uint32_t*)(smem + OFF_A + A_HALF + o) = lo;
            float q0 = sQ[batch * 64 + 2 * pp], q1 = sQ[batch * 64 + 2 * pp + 1];
            split_pair(kv.x * q0, kv.y * q1, hi, lo);
            o = boffA(row, 64 + 2 * pp);
            *(uint32_t*)(smem + OFF_A + o) = hi;
            *(uint32_t*)(smem + OFF_A + A_HALF + o) = lo;
        }
        // ---- c[batch][h] = b0[h] + q . Wq[:,h]  (overlaid on sScore) ----
        if (t < 256) {
            int batch = t >> 7, h = t & 127;
            float acc = b0_g[h];
            #pragma unroll 8
            for (int e = 0; e < NE; e++) acc = fmaf(sQ[batch * 64 + e], g_Wq[e * NH1 + h], acc);
            sScore[t] = acc;   // c value
        }
        __syncthreads();

        // ================= GEMM1: D1[256 x 128] = Kp @ Wcat =================
        float acc[16][4];
        #pragma unroll
        for (int i = 0; i < 16; i++)
            #pragma unroll
            for (int j = 0; j < 4; j++) acc[i][j] = 0.f;

        #pragma unroll
        for (int k = 0; k < 8; k++) {
            const uint32_t kbA = ((k < 4) ? k * 32u : 32768u + (k - 4) * 32u) ^ hsxA;
            const uint32_t kbB = ((k < 4) ? k * 32u : 16384u + (k - 4) * 32u) ^ hsxB;
            uint32_t ah0[4], ah1[4], al0[4], al1[4];
            ldsm4(ah0, aBase + kbA);
            ldsm4(ah1, aBase + 2048 + kbA);
            ldsm4(al0, aBase + A_HALF + kbA);
            ldsm4(al1, aBase + A_HALF + 2048 + kbA);
            #pragma unroll
            for (int np = 0; np < 4; np++) {
                uint32_t bh[4], bl[4];
                const uint32_t ab = b1Base + np * 2048 + kbB;
                ldsm4(bh, ab);
                ldsm4(bl, ab + B1_HALF);
                #pragma unroll
                for (int half = 0; half < 2; half++) {
                    const int nt = np * 2 + half;
                    const uint32_t bh0 = bh[half * 2], bh1 = bh[half * 2 + 1];
                    const uint32_t bl0 = bl[half * 2], bl1 = bl[half * 2 + 1];
                    mma_bf16(acc[nt], ah0, bh0, bh1);
                    mma_bf16(acc[nt], ah0, bl0, bl1);
                    mma_bf16(acc[nt], al0, bh0, bh1);
                    mma_bf16(acc[8 + nt], ah1, bh0, bh1);
                    mma_bf16(acc[8 + nt], ah1, bl0, bl1);
                    mma_bf16(acc[8 + nt], al1, bh0, bh1);
                }
            }
        }
        __syncthreads();   // all A reads done

        // ---- epilogue1: H0 = relu(D1 + c) -> split -> A region ----
        {
            const float* sCb = sScore + batchw * 128;
            #pragma unroll
            for (int mt = 0; mt < 2; mt++) {
                #pragma unroll
                for (int nt = 0; nt < 8; nt++) {
                    const float* c = acc[mt * 8 + nt];
                    const int row = s0 + mt * 16 + (lane >> 2);
                    const int col = h0 + nt * 8 + (lane & 3) * 2;
                    const float c0 = sCb[col], c1 = sCb[col + 1];
                    uint32_t hi, lo, o;
                    split_pair(fmaxf(c[0] + c0, 0.f), fmaxf(c[1] + c1, 0.f), hi, lo);
                    o = boffA(row, col);
                    *(uint32_t*)(smem + OFF_A + o) = hi;
                    *(uint32_t*)(smem + OFF_A + A_HALF + o) = lo;
                    split_pair(fmaxf(c[2] + c0, 0.f), fmaxf(c[3] + c1, 0.f), hi, lo);
                    o = boffA(row + 8, col);
                    *(uint32_t*)(smem + OFF_A + o) = hi;
                    *(uint32_t*)(smem + OFF_A + A_HALF + o) = lo;
                }
            }
        }
        __syncthreads();

        // ================= GEMM2: D2[256 x 64] = H0 @ W1 =================
        float acc2[8][4];
        #pragma unroll
        for (int i = 0; i < 8; i++)
            #pragma unroll
            for (int j = 0; j < 4; j++) acc2[i][j] = 0.f;

        #pragma unroll
        for (int k = 0; k < 8; k++) {
            const uint32_t kbA = ((k < 4) ? k * 32u : 32768u + (k - 4) * 32u) ^ hsxA;
            const uint32_t kbB = ((k < 4) ? k * 32u : 8192u + (k - 4) * 32u) ^ hsxB;
            uint32_t ah0[4], ah1[4], al0[4], al1[4];
            ldsm4(ah0, aBase + kbA);
            ldsm4(ah1, aBase + 2048 + kbA);
            ldsm4(al0, aBase + A_HALF + kbA);
            ldsm4(al1, aBase + A_HALF + 2048 + kbA);
            #pragma unroll
            for (int np = 0; np < 2; np++) {
                uint32_t bh[4], bl[4];
                const uint32_t ab = b2Base + np * 2048 + kbB;
                ldsm4(bh, ab);
                ldsm4(bl, ab + B2_HALF);
                #pragma unroll
                for (int half = 0; half < 2; half++) {
                    const int nt = np * 2 + half;
                    const uint32_t bh0 = bh[half * 2], bh1 = bh[half * 2 + 1];
                    const uint32_t bl0 = bl[half * 2], bl1 = bl[half * 2 + 1];
                    mma_bf16(acc2[nt], ah0, bh0, bh1);
                    mma_bf16(acc2[nt], ah0, bl0, bl1);
                    mma_bf16(acc2[nt], al0, bh0, bh1);
                    mma_bf16(acc2[4 + nt], ah1, bh0, bh1);
                    mma_bf16(acc2[4 + nt], ah1, bl0, bl1);
                    mma_bf16(acc2[4 + nt], al1, bh0, bh1);
                }
            }
        }
        __syncthreads();   // A reads done; A region becomes scratch

        // ---- epilogue2: partial scores -> sPart (in A region) ----
        {
            float part[4] = {0.f, 0.f, 0.f, 0.f};
            #pragma unroll
            for (int mt = 0; mt < 2; mt++) {
                #pragma unroll
                for (int nt = 0; nt < 4; nt++) {
                    const float* c = acc2[mt * 4 + nt];
                    const int col = j0 + nt * 8 + (lane & 3) * 2;
                    const float bb0 = sB1b[col], bb1 = sB1b[col + 1];
                    const float w0v = sW2[col], w1v = sW2[col + 1];
                    part[mt * 2]     += fmaxf(c[0] + bb0, 0.f) * w0v + fmaxf(c[1] + bb1, 0.f) * w1v;
                    part[mt * 2 + 1] += fmaxf(c[2] + bb0, 0.f) * w0v + fmaxf(c[3] + bb1, 0.f) * w1v;
                }
            }
            #pragma unroll
            for (int i = 0; i < 4; i++) {
                float v = part[i];
                v += __shfl_xor_sync(0xffffffffu, v, 1);
                v += __shfl_xor_sync(0xffffffffu, v, 2);
                if ((lane & 3) == 0) {
                    const int row = s0 + (i >> 1) * 16 + (lane >> 2) + (i & 1) * 8;
                    sPart[row * 2 + ng] = v;
                }
            }
        }
        __syncthreads();
        if (t < 256) sScore[t] = sPart[t * 2] + sPart[t * 2 + 1] + b2v;
        __syncthreads();

        // ---- masked softmax: warp 0 -> batch 0, warp 1 -> batch 1 ----
        if (t < 64) {
            const int batch = t >> 5;
            float* sc = sScore + batch * 128;
            const int len = klen_g[gb0 + batch];
            float m = -1e30f;
            for (int s = lane; s < NS; s += 32) {
                float v = (s < len) ? sc[s] : -1e30f;
                m = fmaxf(m, v);
            }
            #pragma unroll
            for (int off = 16; off; off >>= 1)
                m = fmaxf(m, __shfl_xor_sync(0xffffffffu, m, off));
            float sum = 0.f;
            for (int s = lane; s < NS; s += 32) {
                float v = (s < len) ? expf(sc[s] - m) : 0.f;
                sc[s] = v;
                sum += v;
            }
            #pragma unroll
            for (int off = 16; off; off >>= 1)
                sum += __shfl_xor_sync(0xffffffffu, sum, off);
            float inv = 1.f / sum;
            for (int s = lane; s < NS; s += 32) sc[s] *= inv;
        }
        __syncthreads();

        // ---- out[e] = sum_s attn[s] * keys[s][e] ----
        {
            const int batch = t >> 8, e = t & 63, g = (t >> 6) & 3;
            const float* kb = keys_g + (gb0 + batch) * NS * NE;
            const float* sc = sScore + batch * 128;
            float a = 0.f;
            for (int s = g; s < NS; s += 4) a = fmaf(sc[s], kb[s * NE + e], a);
            sPOut[batch * 256 + g * 64 + e] = a;
        }
        __syncthreads();
        if (t < 128) {
            const int batch = t >> 6, e = t & 63;
            const float* po = sPOut + batch * 256;
            out_g[(gb0 + batch) * NE + e] = po[e] + po[64 + e] + po[128 + e] + po[192 + e];
        }
        if (attn_g && t < 256) {
            const int batch = t >> 7, s = t & 127;
            if (s < NS) attn_g[(gb0 + batch) * NS + s] = sScore[batch * 128 + s];
        }
        __syncthreads();   // protect A/sScore reuse next iteration
    }
}

extern "C" void kernel_launch(void* const* d_in, const int* in_sizes, int n_in,
                              void* d_out, int out_size) {
    const float* query = (const float*)d_in[0];
    const float* keys  = (const float*)d_in[1];
    const int*   klen  = (const int*)  d_in[2];
    const float* W0    = (const float*)d_in[3];
    const float* b0    = (const float*)d_in[4];
    const float* W1    = (const float*)d_in[5];
    const float* b1    = (const float*)d_in[6];
    const float* W2    = (const float*)d_in[7];
    const float* b2    = (const float*)d_in[8];

    float* outp  = (float*)d_out;
    float* attnp = (out_size >= NB * NE + NB * NS) ? outp + (size_t)NB * NE : nullptr;

    int dev = 0, nsm = 148;
    cudaGetDevice(&dev);
    cudaDeviceGetAttribute(&nsm, cudaDevAttrMultiProcessorCount, dev);

    cudaFuncSetAttribute(din_kernel, cudaFuncAttributeMaxDynamicSharedMemorySize, SMEM_TOTAL);

    prep_kernel<<<64, 512>>>(W0, W1);
    din_kernel<<<nsm, 512, SMEM_TOTAL>>>(query, keys, klen, b0, b1, W2, b2,
                                         outp, attnp, NB / 2);
}

// round 11
// speedup vs baseline: 1.6988x; 1.0014x over previous
#include <cuda_runtime.h>
#include <cuda_bf16.h>
#include <cstdint>

#define NB   8192
#define NS   100
#define NE   64
#define NH1  128
#define NH2  64
#define NTHREADS 448   // 14 warps: 7 m-groups x 2 n-groups, M-tile 224

// ---- smem layout (bytes) ----
#define OFF_A     0                 // A hi [224 rows x 128k] swizzled nar=28
#define A_HALF    57344             // + lo
#define OFF_B1    114688            // B1 hi (32768) + lo (32768)
#define B1_HALF   32768
#define OFF_B2    180224            // B2 hi (16384) + lo (16384)
#define B2_HALF   16384
#define OFF_W2    212992            // W2[64] f32
#define OFF_B1B   213248            // b1[64] f32
#define OFF_C     213504            // c[2][128] f32
#define OFF_SCORE 214528            // attn scores [2][128] f32
#define OFF_PART  215552            // score partials [224][2] f32
#define OFF_POUT  217344            // out partials [2][2][64] f32
#define SMEM_TOTAL 218368

// ---- device scratch: pre-split, pre-swizzled weights ----
__device__ uint4 g_B1[2][2048];   // hi/lo 32KB each, [128n][128k] swizzled nar=16
__device__ uint4 g_B2[2][1024];   // hi/lo 16KB each, [64n][128k]  swizzled nar=8
__device__ float g_Wq[NE * NH1];  // [e][h] = W0a + W0d

// ================= helpers =================
__device__ __forceinline__ uint32_t smem_u32(const void* p) {
    uint32_t a;
    asm("{ .reg .u64 t; cvta.to.shared.u64 t, %1; cvt.u32.u64 %0, t; }" : "=r"(a) : "l"(p));
    return a;
}
__device__ __forceinline__ void ldsm4(uint32_t* r, uint32_t addr) {
    asm volatile("ldmatrix.sync.aligned.m8n8.x4.shared.b16 {%0,%1,%2,%3}, [%4];"
                 : "=r"(r[0]), "=r"(r[1]), "=r"(r[2]), "=r"(r[3]) : "r"(addr));
}
__device__ __forceinline__ void mma_bf16(float* c, const uint32_t* a, uint32_t b0, uint32_t b1) {
    asm volatile("mma.sync.aligned.m16n8k16.row.col.f32.bf16.bf16.f32 "
                 "{%0,%1,%2,%3}, {%4,%5,%6,%7}, {%8,%9}, {%0,%1,%2,%3};"
                 : "+f"(c[0]), "+f"(c[1]), "+f"(c[2]), "+f"(c[3])
                 : "r"(a[0]), "r"(a[1]), "r"(a[2]), "r"(a[3]), "r"(b0), "r"(b1));
}
__device__ __forceinline__ uint32_t cvt_bf16x2(float lo, float hi) {
    uint32_t r;
    asm("cvt.rn.bf16x2.f32 %0, %1, %2;" : "=r"(r) : "f"(hi), "f"(lo));
    return r;
}
__device__ __forceinline__ void split_pair(float x0, float x1, uint32_t& hi2, uint32_t& lo2) {
    hi2 = cvt_bf16x2(x0, x1);
    float h0 = __uint_as_float(hi2 << 16);
    float h1 = __uint_as_float(hi2 & 0xffff0000u);
    lo2 = cvt_bf16x2(x0 - h0, x1 - h1);
}
// swizzled byte offset in A (nar=28): row 0..223, k elem 0..127
__device__ __forceinline__ uint32_t boffA(int row, int k) {
    return (uint32_t)((((row >> 3) + (k >> 6) * 28) << 10) + ((row & 7) << 7)
                      + ((((k & 63) << 1)) ^ ((row & 7) << 4)));
}
// generic swizzled offset for prep (nar = rows/8)
__device__ __forceinline__ uint32_t boffB(int n, int k, int nar) {
    return (uint32_t)((((n >> 3) + (k >> 6) * nar) << 10) + ((n & 7) << 7)
                      + ((((k & 63) << 1)) ^ ((n & 7) << 4)));
}

// ================= prep: fold + split + swizzle weights =================
__global__ void prep_kernel(const float* __restrict__ W0, const float* __restrict__ W1) {
    int gid = blockIdx.x * blockDim.x + threadIdx.x;
    if (gid < 16384) {                 // B1: n=h, k=f -> Wcat[f][h]
        int n = gid >> 7, k = gid & 127;
        float v;
        if (k < 64) v = W0[(64 + k) * NH1 + n] - W0[(192 + k) * NH1 + n];
        else        v = W0[(128 + (k - 64)) * NH1 + n];
        __nv_bfloat16 h = __float2bfloat16(v);
        uint32_t off = boffB(n, k, 16);
        *(__nv_bfloat16*)((char*)&g_B1[0][0] + off) = h;
        *(__nv_bfloat16*)((char*)&g_B1[1][0] + off) =
            __float2bfloat16(v - __bfloat162float(h));
    } else if (gid < 24576) {          // B2: n=j, k=h -> W1[h][j]
        int i = gid - 16384;
        int n = i >> 7, k = i & 127;
        float v = W1[k * NH2 + n];
        __nv_bfloat16 h = __float2bfloat16(v);
        uint32_t off = boffB(n, k, 8);
        *(__nv_bfloat16*)((char*)&g_B2[0][0] + off) = h;
        *(__nv_bfloat16*)((char*)&g_B2[1][0] + off) =
            __float2bfloat16(v - __bfloat162float(h));
    } else if (gid < 32768) {          // Wq = W0a + W0d
        int i = gid - 24576;
        int e = i >> 7, hh = i & 127;
        g_Wq[e * NH1 + hh] = W0[e * NH1 + hh] + W0[(192 + e) * NH1 + hh];
    }
}

// ================= persistent fused kernel: 448 threads, 2 batches/iter =================
__global__ __launch_bounds__(NTHREADS, 1)
void din_kernel(const float* __restrict__ q_g,
                const float* __restrict__ keys_g,
                const int*   __restrict__ klen_g,
                const float* __restrict__ b0_g,
                const float* __restrict__ b1_g,
                const float* __restrict__ W2_g,
                const float* __restrict__ b2_g,
                float* __restrict__ out_g,
                float* __restrict__ attn_g,
                int npairs) {
    extern __shared__ char smem[];
    const uint32_t sbase = smem_u32(smem);
    float* sW2    = (float*)(smem + OFF_W2);
    float* sB1b   = (float*)(smem + OFF_B1B);
    float* sC     = (float*)(smem + OFF_C);
    float* sScore = (float*)(smem + OFF_SCORE);
    float* sPart  = (float*)(smem + OFF_PART);
    float* sPOut  = (float*)(smem + OFF_POUT);

    const int t = threadIdx.x;
    const int lane = t & 31, w = t >> 5;
    const float b2v = b2_g[0];

    // ---- weights -> smem ONCE ----
    {
        const uint4* s1 = &g_B1[0][0];
        uint4* d1 = (uint4*)(smem + OFF_B1);
        for (int i = t; i < 4096; i += NTHREADS) d1[i] = s1[i];
        const uint4* s2 = &g_B2[0][0];
        uint4* d2 = (uint4*)(smem + OFF_B2);
        for (int i = t; i < 2048; i += NTHREADS) d2[i] = s2[i];
        if (t < 64) { sW2[t] = W2_g[t]; sB1b[t] = b1_g[t]; }
    }

    // ---- lane geometry (constant across iterations) ----
    const int mg = w >> 1, ng = w & 1;
    const int s0 = mg * 32;                    // warp row base (0..192)
    const int rA = s0 + (lane & 15);
    const uint32_t aBase = sbase + OFF_A + ((rA >> 3) << 10) + ((rA & 7) << 7);
    const uint32_t hsxA = (((lane >> 4) & 1) * 16) ^ ((lane & 7) << 4);
    const uint32_t hsxB = (((lane >> 3) & 1) * 16) ^ ((lane & 7) << 4);
    const int h0 = ng * 64, j0 = ng * 32;
    const uint32_t b1Base = sbase + OFF_B1 + (((h0 >> 3) + ((lane >> 4) & 1)) << 10)
                          + ((lane & 7) << 7);
    const uint32_t b2Base = sbase + OFF_B2 + (((j0 >> 3) + ((lane >> 4) & 1)) << 10)
                          + ((lane & 7) << 7);

    for (int p = blockIdx.x; p < npairs; p += gridDim.x) {
        const long gb0 = (long)p * 2;

        // ---- build Kp (rows: batch0 -> 0..99, batch1 -> 100..199) ----
        for (int i = t; i < 6400; i += NTHREADS) {
            int batch = (i >= 3200), rem = i - batch * 3200;
            int s = rem >> 5, pp = rem & 31;
            int row = batch * 100 + s;
            float2 kv = *(const float2*)&keys_g[((gb0 + batch) * NS + s) * NE + 2 * pp];
            float2 qv = *(const float2*)&q_g[(gb0 + batch) * NE + 2 * pp];
            uint32_t hi, lo;
            split_pair(kv.x, kv.y, hi, lo);
            uint32_t o = boffA(row, 2 * pp);
            *(uint32_t*)(smem + OFF_A + o) = hi;
            *(uint32_t*)(smem + OFF_A + A_HALF + o) = lo;
            split_pair(kv.x * qv.x, kv.y * qv.y, hi, lo);
            o = boffA(row, 64 + 2 * pp);
            *(uint32_t*)(smem + OFF_A + o) = hi;
            *(uint32_t*)(smem + OFF_A + A_HALF + o) = lo;
        }
        // ---- c[batch][h] = b0[h] + q . Wq[:,h] ----
        if (t < 256) {
            int batch = t >> 7, h = t & 127;
            const float* qb = q_g + (gb0 + batch) * NE;
            float acc = b0_g[h];
            #pragma unroll 8
            for (int e = 0; e < NE; e++) acc = fmaf(qb[e], g_Wq[e * NH1 + h], acc);
            sC[t] = acc;
        }
        __syncthreads();

        // ================= GEMM1: D1[224 x 128] = Kp @ Wcat =================
        float acc[16][4];
        #pragma unroll
        for (int i = 0; i < 16; i++)
            #pragma unroll
            for (int j = 0; j < 4; j++) acc[i][j] = 0.f;

        #pragma unroll
        for (int k = 0; k < 8; k++) {
            const uint32_t kbA = ((k < 4) ? k * 32u : 28672u + (k - 4) * 32u) ^ hsxA;
            const uint32_t kbB = ((k < 4) ? k * 32u : 16384u + (k - 4) * 32u) ^ hsxB;
            uint32_t ah0[4], ah1[4], al0[4], al1[4];
            ldsm4(ah0, aBase + kbA);
            ldsm4(ah1, aBase + 2048 + kbA);
            ldsm4(al0, aBase + A_HALF + kbA);
            ldsm4(al1, aBase + A_HALF + 2048 + kbA);
            #pragma unroll
            for (int np = 0; np < 4; np++) {
                uint32_t bh[4], bl[4];
                const uint32_t ab = b1Base + np * 2048 + kbB;
                ldsm4(bh, ab);
                ldsm4(bl, ab + B1_HALF);
                #pragma unroll
                for (int half = 0; half < 2; half++) {
                    const int nt = np * 2 + half;
                    const uint32_t bh0 = bh[half * 2], bh1 = bh[half * 2 + 1];
                    const uint32_t bl0 = bl[half * 2], bl1 = bl[half * 2 + 1];
                    mma_bf16(acc[nt],     ah0, bh0, bh1);
                    mma_bf16(acc[8 + nt], ah1, bh0, bh1);
                    mma_bf16(acc[nt],     ah0, bl0, bl1);
                    mma_bf16(acc[8 + nt], ah1, bl0, bl1);
                    mma_bf16(acc[nt],     al0, bh0, bh1);
                    mma_bf16(acc[8 + nt], al1, bh0, bh1);
                }
            }
        }
        __syncthreads();   // all A reads done

        // ---- epilogue1: H0 = relu(D1 + c) -> split -> A region ----
        #pragma unroll
        for (int mt = 0; mt < 2; mt++) {
            #pragma unroll
            for (int nt = 0; nt < 8; nt++) {
                const float* c = acc[mt * 8 + nt];
                const int row = s0 + mt * 16 + (lane >> 2);
                const int col = h0 + nt * 8 + (lane & 3) * 2;
                const int cbase = (row >= 100 ? 128 : 0) + col;
                const float c0 = sC[cbase], c1 = sC[cbase + 1];
                const int cbase8 = (row + 8 >= 100 ? 128 : 0) + col;
                const float d0 = sC[cbase8], d1 = sC[cbase8 + 1];
                uint32_t hi, lo, o;
                split_pair(fmaxf(c[0] + c0, 0.f), fmaxf(c[1] + c1, 0.f), hi, lo);
                o = boffA(row, col);
                *(uint32_t*)(smem + OFF_A + o) = hi;
                *(uint32_t*)(smem + OFF_A + A_HALF + o) = lo;
                split_pair(fmaxf(c[2] + d0, 0.f), fmaxf(c[3] + d1, 0.f), hi, lo);
                o = boffA(row + 8, col);
                *(uint32_t*)(smem + OFF_A + o) = hi;
                *(uint32_t*)(smem + OFF_A + A_HALF + o) = lo;
            }
        }
        __syncthreads();

        // ================= GEMM2: D2[224 x 64] = H0 @ W1 =================
        float acc2[8][4];
        #pragma unroll
        for (int i = 0; i < 8; i++)
            #pragma unroll
            for (int j = 0; j < 4; j++) acc2[i][j] = 0.f;

        #pragma unroll
        for (int k = 0; k < 8; k++) {
            const uint32_t kbA = ((k < 4) ? k * 32u : 28672u + (k - 4) * 32u) ^ hsxA;
            const uint32_t kbB = ((k < 4) ? k * 32u : 8192u + (k - 4) * 32u) ^ hsxB;
            uint32_t ah0[4], ah1[4], al0[4], al1[4];
            ldsm4(ah0, aBase + kbA);
            ldsm4(ah1, aBase + 2048 + kbA);
            ldsm4(al0, aBase + A_HALF + kbA);
            ldsm4(al1, aBase + A_HALF + 2048 + kbA);
            #pragma unroll
            for (int np = 0; np < 2; np++) {
                uint32_t bh[4], bl[4];
                const uint32_t ab = b2Base + np * 2048 + kbB;
                ldsm4(bh, ab);
                ldsm4(bl, ab + B2_HALF);
                #pragma unroll
                for (int half = 0; half < 2; half++) {
                    const int nt = np * 2 + half;
                    const uint32_t bh0 = bh[half * 2], bh1 = bh[half * 2 + 1];
                    const uint32_t bl0 = bl[half * 2], bl1 = bl[half * 2 + 1];
                    mma_bf16(acc2[nt],     ah0, bh0, bh1);
                    mma_bf16(acc2[4 + nt], ah1, bh0, bh1);
                    mma_bf16(acc2[nt],     ah0, bl0, bl1);
                    mma_bf16(acc2[4 + nt], ah1, bl0, bl1);
                    mma_bf16(acc2[nt],     al0, bh0, bh1);
                    mma_bf16(acc2[4 + nt], al1, bh0, bh1);
                }
            }
        }
        __syncthreads();

        // ---- epilogue2: partial scores -> sPart ----
        {
            float part[4] = {0.f, 0.f, 0.f, 0.f};
            #pragma unroll
            for (int mt = 0; mt < 2; mt++) {
                #pragma unroll
                for (int nt = 0; nt < 4; nt++) {
                    const float* c = acc2[mt * 4 + nt];
                    const int col = j0 + nt * 8 + (lane & 3) * 2;
                    const float bb0 = sB1b[col], bb1 = sB1b[col + 1];
                    const float w0v = sW2[col], w1v = sW2[col + 1];
                    part[mt * 2]     += fmaxf(c[0] + bb0, 0.f) * w0v + fmaxf(c[1] + bb1, 0.f) * w1v;
                    part[mt * 2 + 1] += fmaxf(c[2] + bb0, 0.f) * w0v + fmaxf(c[3] + bb1, 0.f) * w1v;
                }
            }
            #pragma unroll
            for (int i = 0; i < 4; i++) {
                float v = part[i];
                v += __shfl_xor_sync(0xffffffffu, v, 1);
                v += __shfl_xor_sync(0xffffffffu, v, 2);
                if ((lane & 3) == 0) {
                    const int row = s0 + (i >> 1) * 16 + (lane >> 2) + (i & 1) * 8;
                    sPart[row * 2 + ng] = v;
                }
            }
        }
        __syncthreads();

        // ---- masked softmax + attn store: warp 0 -> batch0, warp 1 -> batch1 ----
        if (t < 64) {
            const int batch = t >> 5;
            float* sc = sScore + batch * 128;
            const float* pp = sPart + batch * 200;   // rows batch*100.. -> sPart[(b*100+s)*2]
            const int len = klen_g[gb0 + batch];
            float m = -1e30f;
            float sv[4];
            #pragma unroll
            for (int i = 0; i < 4; i++) {
                int s = lane + i * 32;
                float v = -1e30f;
                if (s < NS) {
                    v = pp[s * 2] + pp[s * 2 + 1] + b2v;
                    if (s >= len) v = -1e30f;
                }
                sv[i] = v;
                m = fmaxf(m, v);
            }
            #pragma unroll
            for (int off = 16; off; off >>= 1)
                m = fmaxf(m, __shfl_xor_sync(0xffffffffu, m, off));
            float sum = 0.f;
            #pragma unroll
            for (int i = 0; i < 4; i++) {
                int s = lane + i * 32;
                float v = (s < len) ? expf(sv[i] - m) : 0.f;
                sv[i] = v;
                sum += v;
            }
            #pragma unroll
            for (int off = 16; off; off >>= 1)
                sum += __shfl_xor_sync(0xffffffffu, sum, off);
            float inv = 1.f / sum;
            #pragma unroll
            for (int i = 0; i < 4; i++) {
                int s = lane + i * 32;
                if (s < NS) {
                    float a = sv[i] * inv;
                    sc[s] = a;
                    if (attn_g) attn_g[(gb0 + batch) * NS + s] = a;
                }
            }
        }
        __syncthreads();

        // ---- out[e] = sum_s attn[s] * keys[s][e] ----
        if (t < 256) {
            const int batch = t >> 7, rem = t & 127, g = rem >> 6, e = rem & 63;
            const float* kb = keys_g + (gb0 + batch) * NS * NE;
            const float* sc = sScore + batch * 128;
            float a = 0.f;
            for (int s = g; s < NS; s += 2) a = fmaf(sc[s], kb[s * NE + e], a);
            sPOut[batch * 128 + g * 64 + e] = a;
        }
        __syncthreads();
        if (t < 128) {
            const int batch = t >> 6, e = t & 63;
            out_g[(gb0 + batch) * NE + e] = sPOut[batch * 128 + e] + sPOut[batch * 128 + 64 + e];
        }
        // no trailing barrier needed: next iteration writes only A/sC before sync1,
        // which nothing here still reads.
    }
}

extern "C" void kernel_launch(void* const* d_in, const int* in_sizes, int n_in,
                              void* d_out, int out_size) {
    const float* query = (const float*)d_in[0];
    const float* keys  = (const float*)d_in[1];
    const int*   klen  = (const int*)  d_in[2];
    const float* W0    = (const float*)d_in[3];
    const float* b0    = (const float*)d_in[4];
    const float* W1    = (const float*)d_in[5];
    const float* b1    = (const float*)d_in[6];
    const float* W2    = (const float*)d_in[7];
    const float* b2    = (const float*)d_in[8];

    float* outp  = (float*)d_out;
    float* attnp = (out_size >= NB * NE + NB * NS) ? outp + (size_t)NB * NE : nullptr;

    int dev = 0, nsm = 148;
    cudaGetDevice(&dev);
    cudaDeviceGetAttribute(&nsm, cudaDevAttrMultiProcessorCount, dev);

    cudaFuncSetAttribute(din_kernel, cudaFuncAttributeMaxDynamicSharedMemorySize, SMEM_TOTAL);

    prep_kernel<<<64, 512>>>(W0, W1);
    din_kernel<<<nsm, NTHREADS, SMEM_TOTAL>>>(query, keys, klen, b0, b1, W2, b2,
                                              outp, attnp, NB / 2);
}

// round 12
// speedup vs baseline: 1.9506x; 1.1482x over previous
#include <cuda_runtime.h>
#include <cuda_bf16.h>
#include <cstdint>

#define NB   8192
#define NS   100
#define NE   64
#define NH1  128
#define NH2  64
#define NTHREADS 896   // 28 warps: 14 m-groups (16 rows) x 2 n-groups, M-tile 224

// ---- smem layout (bytes) ----
#define OFF_A     0                 // A hi [224 rows x 128k] swizzled nar=28
#define A_HALF    57344             // + lo
#define OFF_B1    114688            // B1 hi (32768) + lo (32768)
#define B1_HALF   32768
#define OFF_B2    180224            // B2 hi (16384) + lo (16384)
#define B2_HALF   16384
#define OFF_W2    212992            // W2[64] f32
#define OFF_B1B   213248            // b1[64] f32
#define OFF_C     213504            // c[2][128] f32
#define OFF_SCORE 214528            // attn scores [2][128] f32
#define OFF_PART  215552            // score partials [224][2] f32
#define OFF_POUT  217344            // out partials [2][2][64] f32
#define SMEM_TOTAL 218368

// ---- device scratch: pre-split, pre-swizzled weights ----
__device__ uint4 g_B1[2][2048];   // hi/lo 32KB each, [128n][128k] swizzled nar=16
__device__ uint4 g_B2[2][1024];   // hi/lo 16KB each, [64n][128k]  swizzled nar=8
__device__ float g_Wq[NE * NH1];  // [e][h] = W0a + W0d

// ================= helpers =================
__device__ __forceinline__ uint32_t smem_u32(const void* p) {
    uint32_t a;
    asm("{ .reg .u64 t; cvta.to.shared.u64 t, %1; cvt.u32.u64 %0, t; }" : "=r"(a) : "l"(p));
    return a;
}
__device__ __forceinline__ void ldsm4(uint32_t* r, uint32_t addr) {
    asm volatile("ldmatrix.sync.aligned.m8n8.x4.shared.b16 {%0,%1,%2,%3}, [%4];"
                 : "=r"(r[0]), "=r"(r[1]), "=r"(r[2]), "=r"(r[3]) : "r"(addr));
}
__device__ __forceinline__ void mma_bf16(float* c, const uint32_t* a, uint32_t b0, uint32_t b1) {
    asm volatile("mma.sync.aligned.m16n8k16.row.col.f32.bf16.bf16.f32 "
                 "{%0,%1,%2,%3}, {%4,%5,%6,%7}, {%8,%9}, {%0,%1,%2,%3};"
                 : "+f"(c[0]), "+f"(c[1]), "+f"(c[2]), "+f"(c[3])
                 : "r"(a[0]), "r"(a[1]), "r"(a[2]), "r"(a[3]), "r"(b0), "r"(b1));
}
__device__ __forceinline__ uint32_t cvt_bf16x2(float lo, float hi) {
    uint32_t r;
    asm("cvt.rn.bf16x2.f32 %0, %1, %2;" : "=r"(r) : "f"(hi), "f"(lo));
    return r;
}
__device__ __forceinline__ void split_pair(float x0, float x1, uint32_t& hi2, uint32_t& lo2) {
    hi2 = cvt_bf16x2(x0, x1);
    float h0 = __uint_as_float(hi2 << 16);
    float h1 = __uint_as_float(hi2 & 0xffff0000u);
    lo2 = cvt_bf16x2(x0 - h0, x1 - h1);
}
// swizzled byte offset in A (nar=28): row 0..223, k elem 0..127
__device__ __forceinline__ uint32_t boffA(int row, int k) {
    return (uint32_t)((((row >> 3) + (k >> 6) * 28) << 10) + ((row & 7) << 7)
                      + ((((k & 63) << 1)) ^ ((row & 7) << 4)));
}
// generic swizzled offset for prep (nar = rows/8)
__device__ __forceinline__ uint32_t boffB(int n, int k, int nar) {
    return (uint32_t)((((n >> 3) + (k >> 6) * nar) << 10) + ((n & 7) << 7)
                      + ((((k & 63) << 1)) ^ ((n & 7) << 4)));
}

// ================= prep: fold + split + swizzle weights =================
__global__ void prep_kernel(const float* __restrict__ W0, const float* __restrict__ W1) {
    int gid = blockIdx.x * blockDim.x + threadIdx.x;
    if (gid < 16384) {                 // B1: n=h, k=f -> Wcat[f][h]
        int n = gid >> 7, k = gid & 127;
        float v;
        if (k < 64) v = W0[(64 + k) * NH1 + n] - W0[(192 + k) * NH1 + n];
        else        v = W0[(128 + (k - 64)) * NH1 + n];
        __nv_bfloat16 h = __float2bfloat16(v);
        uint32_t off = boffB(n, k, 16);
        *(__nv_bfloat16*)((char*)&g_B1[0][0] + off) = h;
        *(__nv_bfloat16*)((char*)&g_B1[1][0] + off) =
            __float2bfloat16(v - __bfloat162float(h));
    } else if (gid < 24576) {          // B2: n=j, k=h -> W1[h][j]
        int i = gid - 16384;
        int n = i >> 7, k = i & 127;
        float v = W1[k * NH2 + n];
        __nv_bfloat16 h = __float2bfloat16(v);
        uint32_t off = boffB(n, k, 8);
        *(__nv_bfloat16*)((char*)&g_B2[0][0] + off) = h;
        *(__nv_bfloat16*)((char*)&g_B2[1][0] + off) =
            __float2bfloat16(v - __bfloat162float(h));
    } else if (gid < 32768) {          // Wq = W0a + W0d
        int i = gid - 24576;
        int e = i >> 7, hh = i & 127;
        g_Wq[e * NH1 + hh] = W0[e * NH1 + hh] + W0[(192 + e) * NH1 + hh];
    }
}

// ================= persistent fused kernel: 896 threads, 2 batches/iter =================
__global__ __launch_bounds__(NTHREADS, 1)
void din_kernel(const float* __restrict__ q_g,
                const float* __restrict__ keys_g,
                const int*   __restrict__ klen_g,
                const float* __restrict__ b0_g,
                const float* __restrict__ b1_g,
                const float* __restrict__ W2_g,
                const float* __restrict__ b2_g,
                float* __restrict__ out_g,
                float* __restrict__ attn_g,
                int npairs) {
    extern __shared__ char smem[];
    const uint32_t sbase = smem_u32(smem);
    float* sW2    = (float*)(smem + OFF_W2);
    float* sB1b   = (float*)(smem + OFF_B1B);
    float* sC     = (float*)(smem + OFF_C);
    float* sScore = (float*)(smem + OFF_SCORE);
    float* sPart  = (float*)(smem + OFF_PART);
    float* sPOut  = (float*)(smem + OFF_POUT);

    const int t = threadIdx.x;
    const int lane = t & 31, w = t >> 5;
    const float b2v = b2_g[0];

    // ---- weights -> smem ONCE ----
    {
        const uint4* s1 = &g_B1[0][0];
        uint4* d1 = (uint4*)(smem + OFF_B1);
        for (int i = t; i < 4096; i += NTHREADS) d1[i] = s1[i];
        const uint4* s2 = &g_B2[0][0];
        uint4* d2 = (uint4*)(smem + OFF_B2);
        for (int i = t; i < 2048; i += NTHREADS) d2[i] = s2[i];
        if (t < 64) { sW2[t] = W2_g[t]; sB1b[t] = b1_g[t]; }
    }

    // ---- lane geometry (constant across iterations) ----
    const int mg = w >> 1, ng = w & 1;
    const int s0 = mg * 16;                    // warp row base (0..208)
    const int rA = s0 + (lane & 15);
    const uint32_t aBase = sbase + OFF_A + ((rA >> 3) << 10) + ((rA & 7) << 7);
    const uint32_t hsxA = (((lane >> 4) & 1) * 16) ^ ((lane & 7) << 4);
    const uint32_t hsxB = (((lane >> 3) & 1) * 16) ^ ((lane & 7) << 4);
    const int h0 = ng * 64, j0 = ng * 32;
    const uint32_t b1Base = sbase + OFF_B1 + (((h0 >> 3) + ((lane >> 4) & 1)) << 10)
                          + ((lane & 7) << 7);
    const uint32_t b2Base = sbase + OFF_B2 + (((j0 >> 3) + ((lane >> 4) & 1)) << 10)
                          + ((lane & 7) << 7);

    for (int p = blockIdx.x; p < npairs; p += gridDim.x) {
        const long gb0 = (long)p * 2;

        // ---- build Kp (rows: batch0 -> 0..99, batch1 -> 100..199) ----
        for (int i = t; i < 6400; i += NTHREADS) {
            int batch = (i >= 3200), rem = i - batch * 3200;
            int s = rem >> 5, pp = rem & 31;
            int row = batch * 100 + s;
            float2 kv = *(const float2*)&keys_g[((gb0 + batch) * NS + s) * NE + 2 * pp];
            float2 qv = *(const float2*)&q_g[(gb0 + batch) * NE + 2 * pp];
            uint32_t hi, lo;
            split_pair(kv.x, kv.y, hi, lo);
            uint32_t o = boffA(row, 2 * pp);
            *(uint32_t*)(smem + OFF_A + o) = hi;
            *(uint32_t*)(smem + OFF_A + A_HALF + o) = lo;
            split_pair(kv.x * qv.x, kv.y * qv.y, hi, lo);
            o = boffA(row, 64 + 2 * pp);
            *(uint32_t*)(smem + OFF_A + o) = hi;
            *(uint32_t*)(smem + OFF_A + A_HALF + o) = lo;
        }
        // ---- c[batch][h] = b0[h] + q . Wq[:,h] ----
        if (t < 256) {
            int batch = t >> 7, h = t & 127;
            const float* qb = q_g + (gb0 + batch) * NE;
            float acc0 = b0_g[h];
            #pragma unroll 8
            for (int e = 0; e < NE; e++) acc0 = fmaf(qb[e], g_Wq[e * NH1 + h], acc0);
            sC[t] = acc0;
        }
        __syncthreads();

        // ================= GEMM1: D1[224 x 128] = Kp @ Wcat =================
        // warp tile: M=16 (rows s0..s0+15), N=64 (h0..h0+63)
        float acc[8][4];
        #pragma unroll
        for (int i = 0; i < 8; i++)
            #pragma unroll
            for (int j = 0; j < 4; j++) acc[i][j] = 0.f;

        #pragma unroll
        for (int k = 0; k < 8; k++) {
            const uint32_t kbA = ((k < 4) ? k * 32u : 28672u + (k - 4) * 32u) ^ hsxA;
            const uint32_t kbB = ((k < 4) ? k * 32u : 16384u + (k - 4) * 32u) ^ hsxB;
            uint32_t ah0[4], al0[4];
            ldsm4(ah0, aBase + kbA);
            ldsm4(al0, aBase + A_HALF + kbA);
            #pragma unroll
            for (int np = 0; np < 4; np++) {
                uint32_t bh[4], bl[4];
                const uint32_t ab = b1Base + np * 2048 + kbB;
                ldsm4(bh, ab);
                ldsm4(bl, ab + B1_HALF);
                const int nt = np * 2;
                mma_bf16(acc[nt],     ah0, bh[0], bh[1]);
                mma_bf16(acc[nt + 1], ah0, bh[2], bh[3]);
                mma_bf16(acc[nt],     ah0, bl[0], bl[1]);
                mma_bf16(acc[nt + 1], ah0, bl[2], bl[3]);
                mma_bf16(acc[nt],     al0, bh[0], bh[1]);
                mma_bf16(acc[nt + 1], al0, bh[2], bh[3]);
            }
        }
        __syncthreads();   // all A reads done

        // ---- epilogue1: H0 = relu(D1 + c) -> split -> A region ----
        {
            const int row = s0 + (lane >> 2);
            const int cb0 = (row >= 100 ? 128 : 0);
            const int cb8 = (row + 8 >= 100 ? 128 : 0);
            #pragma unroll
            for (int nt = 0; nt < 8; nt++) {
                const float* c = acc[nt];
                const int col = h0 + nt * 8 + (lane & 3) * 2;
                const float c0 = sC[cb0 + col], c1 = sC[cb0 + col + 1];
                const float d0 = sC[cb8 + col], d1 = sC[cb8 + col + 1];
                uint32_t hi, lo, o;
                split_pair(fmaxf(c[0] + c0, 0.f), fmaxf(c[1] + c1, 0.f), hi, lo);
                o = boffA(row, col);
                *(uint32_t*)(smem + OFF_A + o) = hi;
                *(uint32_t*)(smem + OFF_A + A_HALF + o) = lo;
                split_pair(fmaxf(c[2] + d0, 0.f), fmaxf(c[3] + d1, 0.f), hi, lo);
                o = boffA(row + 8, col);
                *(uint32_t*)(smem + OFF_A + o) = hi;
                *(uint32_t*)(smem + OFF_A + A_HALF + o) = lo;
            }
        }
        __syncthreads();

        // ================= GEMM2: D2[224 x 64] = H0 @ W1 =================
        // warp tile: M=16, N=32 (j0..j0+31)
        float acc2[4][4];
        #pragma unroll
        for (int i = 0; i < 4; i++)
            #pragma unroll
            for (int j = 0; j < 4; j++) acc2[i][j] = 0.f;

        #pragma unroll
        for (int k = 0; k < 8; k++) {
            const uint32_t kbA = ((k < 4) ? k * 32u : 28672u + (k - 4) * 32u) ^ hsxA;
            const uint32_t kbB = ((k < 4) ? k * 32u : 8192u + (k - 4) * 32u) ^ hsxB;
            uint32_t ah0[4], al0[4];
            ldsm4(ah0, aBase + kbA);
            ldsm4(al0, aBase + A_HALF + kbA);
            #pragma unroll
            for (int np = 0; np < 2; np++) {
                uint32_t bh[4], bl[4];
                const uint32_t ab = b2Base + np * 2048 + kbB;
                ldsm4(bh, ab);
                ldsm4(bl, ab + B2_HALF);
                const int nt = np * 2;
                mma_bf16(acc2[nt],     ah0, bh[0], bh[1]);
                mma_bf16(acc2[nt + 1], ah0, bh[2], bh[3]);
                mma_bf16(acc2[nt],     ah0, bl[0], bl[1]);
                mma_bf16(acc2[nt + 1], ah0, bl[2], bl[3]);
                mma_bf16(acc2[nt],     al0, bh[0], bh[1]);
                mma_bf16(acc2[nt + 1], al0, bh[2], bh[3]);
            }
        }
        __syncthreads();

        // ---- epilogue2: partial scores -> sPart ----
        {
            float part[2] = {0.f, 0.f};
            #pragma unroll
            for (int nt = 0; nt < 4; nt++) {
                const float* c = acc2[nt];
                const int col = j0 + nt * 8 + (lane & 3) * 2;
                const float bb0 = sB1b[col], bb1 = sB1b[col + 1];
                const float w0v = sW2[col], w1v = sW2[col + 1];
                part[0] += fmaxf(c[0] + bb0, 0.f) * w0v + fmaxf(c[1] + bb1, 0.f) * w1v;
                part[1] += fmaxf(c[2] + bb0, 0.f) * w0v + fmaxf(c[3] + bb1, 0.f) * w1v;
            }
            #pragma unroll
            for (int i = 0; i < 2; i++) {
                float v = part[i];
                v += __shfl_xor_sync(0xffffffffu, v, 1);
                v += __shfl_xor_sync(0xffffffffu, v, 2);
                if ((lane & 3) == 0) {
                    const int row = s0 + (lane >> 2) + i * 8;
                    sPart[row * 2 + ng] = v;
                }
            }
        }
        __syncthreads();

        // ---- masked softmax + attn store: warp 0 -> batch0, warp 1 -> batch1 ----
        if (t < 64) {
            const int batch = t >> 5;
            float* sc = sScore + batch * 128;
            const float* pp = sPart + batch * 200;
            const int len = klen_g[gb0 + batch];
            float m = -1e30f;
            float sv[4];
            #pragma unroll
            for (int i = 0; i < 4; i++) {
                int s = lane + i * 32;
                float v = -1e30f;
                if (s < NS) {
                    v = pp[s * 2] + pp[s * 2 + 1] + b2v;
                    if (s >= len) v = -1e30f;
                }
                sv[i] = v;
                m = fmaxf(m, v);
            }
            #pragma unroll
            for (int off = 16; off; off >>= 1)
                m = fmaxf(m, __shfl_xor_sync(0xffffffffu, m, off));
            float sum = 0.f;
            #pragma unroll
            for (int i = 0; i < 4; i++) {
                int s = lane + i * 32;
                float v = (s < len) ? expf(sv[i] - m) : 0.f;
                sv[i] = v;
                sum += v;
            }
            #pragma unroll
            for (int off = 16; off; off >>= 1)
                sum += __shfl_xor_sync(0xffffffffu, sum, off);
            float inv = 1.f / sum;
            #pragma unroll
            for (int i = 0; i < 4; i++) {
                int s = lane + i * 32;
                if (s < NS) {
                    float a = sv[i] * inv;
                    sc[s] = a;
                    if (attn_g) attn_g[(gb0 + batch) * NS + s] = a;
                }
            }
        }
        __syncthreads();

        // ---- out[e] = sum_s attn[s] * keys[s][e] ----
        if (t < 256) {
            const int batch = t >> 7, rem = t & 127, g = rem >> 6, e = rem & 63;
            const float* kb = keys_g + (gb0 + batch) * NS * NE;
            const float* sc = sScore + batch * 128;
            float a = 0.f;
            for (int s = g; s < NS; s += 2) a = fmaf(sc[s], kb[s * NE + e], a);
            sPOut[batch * 128 + g * 64 + e] = a;
        }
        __syncthreads();
        if (t < 128) {
            const int batch = t >> 6, e = t & 63;
            out_g[(gb0 + batch) * NE + e] = sPOut[batch * 128 + e] + sPOut[batch * 128 + 64 + e];
        }
        // no trailing barrier: next iteration's pre-sync writes (A, sC) are not
        // read by any thread after this point in the current iteration.
    }
}

extern "C" void kernel_launch(void* const* d_in, const int* in_sizes, int n_in,
                              void* d_out, int out_size) {
    const float* query = (const float*)d_in[0];
    const float* keys  = (const float*)d_in[1];
    const int*   klen  = (const int*)  d_in[2];
    const float* W0    = (const float*)d_in[3];
    const float* b0    = (const float*)d_in[4];
    const float* W1    = (const float*)d_in[5];
    const float* b1    = (const float*)d_in[6];
    const float* W2    = (const float*)d_in[7];
    const float* b2    = (const float*)d_in[8];

    float* outp  = (float*)d_out;
    float* attnp = (out_size >= NB * NE + NB * NS) ? outp + (size_t)NB * NE : nullptr;

    int dev = 0, nsm = 148;
    cudaGetDevice(&dev);
    cudaDeviceGetAttribute(&nsm, cudaDevAttrMultiProcessorCount, dev);

    cudaFuncSetAttribute(din_kernel, cudaFuncAttributeMaxDynamicSharedMemorySize, SMEM_TOTAL);

    prep_kernel<<<64, 512>>>(W0, W1);
    din_kernel<<<nsm, NTHREADS, SMEM_TOTAL>>>(query, keys, klen, b0, b1, W2, b2,
                                              outp, attnp, NB / 2);
}

// round 13
// speedup vs baseline: 1.9868x; 1.0186x over previous
#include <cuda_runtime.h>
#include <cuda_bf16.h>
#include <cstdint>

#define NB   8192
#define NS   100
#define NE   64
#define NH1  128
#define NH2  64
#define NTHREADS 896   // 2 halves x 448 threads (14 warps each)
#define HALFT 448

// ---- smem layout (bytes) ----
// Per-half A: [112 rows x 128k] bf16, swizzled nar=14: hi 28672 + lo 28672 = 57344
#define OFF_A     0
#define A_HSZ     57344             // per-half A block (hi+lo)
#define A_PLANE   28672             // hi->lo offset within half
#define OFF_B1    114688            // B1 hi (32768) + lo (32768)
#define B1_HALF   32768
#define OFF_B2    180224            // B2 hi (16384) + lo (16384)
#define B2_HALF   16384
#define OFF_W2    212992            // W2[64] f32
#define OFF_B1B   213248            // b1[64] f32
#define OFF_C     213504            // per-half c[128] f32 (2 x 512)
#define OFF_SCORE 214528            // per-half scores[128] f32 (2 x 512)
#define OFF_PART  215552            // per-half score partials [112][2] f32 (2 x 1024)
#define OFF_POUT  217600            // per-half out partials [2][64] f32 (2 x 512)
#define SMEM_TOTAL 218624

// ---- device scratch: pre-split, pre-swizzled weights ----
__device__ uint4 g_B1[2][2048];   // hi/lo 32KB each, [128n][128k] swizzled nar=16
__device__ uint4 g_B2[2][1024];   // hi/lo 16KB each, [64n][128k]  swizzled nar=8
__device__ float g_Wq[NE * NH1];  // [e][h] = W0a + W0d

// ================= helpers =================
__device__ __forceinline__ uint32_t smem_u32(const void* p) {
    uint32_t a;
    asm("{ .reg .u64 t; cvta.to.shared.u64 t, %1; cvt.u32.u64 %0, t; }" : "=r"(a) : "l"(p));
    return a;
}
__device__ __forceinline__ void barh(int id) {
    asm volatile("bar.sync %0, %1;" :: "r"(id), "r"(HALFT) : "memory");
}
__device__ __forceinline__ void ldsm4(uint32_t* r, uint32_t addr) {
    asm volatile("ldmatrix.sync.aligned.m8n8.x4.shared.b16 {%0,%1,%2,%3}, [%4];"
                 : "=r"(r[0]), "=r"(r[1]), "=r"(r[2]), "=r"(r[3]) : "r"(addr));
}
__device__ __forceinline__ void mma_bf16(float* c, const uint32_t* a, uint32_t b0, uint32_t b1) {
    asm volatile("mma.sync.aligned.m16n8k16.row.col.f32.bf16.bf16.f32 "
                 "{%0,%1,%2,%3}, {%4,%5,%6,%7}, {%8,%9}, {%0,%1,%2,%3};"
                 : "+f"(c[0]), "+f"(c[1]), "+f"(c[2]), "+f"(c[3])
                 : "r"(a[0]), "r"(a[1]), "r"(a[2]), "r"(a[3]), "r"(b0), "r"(b1));
}
__device__ __forceinline__ uint32_t cvt_bf16x2(float lo, float hi) {
    uint32_t r;
    asm("cvt.rn.bf16x2.f32 %0, %1, %2;" : "=r"(r) : "f"(hi), "f"(lo));
    return r;
}
__device__ __forceinline__ void split_pair(float x0, float x1, uint32_t& hi2, uint32_t& lo2) {
    hi2 = cvt_bf16x2(x0, x1);
    float h0 = __uint_as_float(hi2 << 16);
    float h1 = __uint_as_float(hi2 & 0xffff0000u);
    lo2 = cvt_bf16x2(x0 - h0, x1 - h1);
}
// swizzled byte offset in per-half A (nar=14): row 0..111, k elem 0..127
__device__ __forceinline__ uint32_t boffA(int row, int k) {
    return (uint32_t)((((row >> 3) + (k >> 6) * 14) << 10) + ((row & 7) << 7)
                      + ((((k & 63) << 1)) ^ ((row & 7) << 4)));
}
// generic swizzled offset for prep (nar = rows/8)
__device__ __forceinline__ uint32_t boffB(int n, int k, int nar) {
    return (uint32_t)((((n >> 3) + (k >> 6) * nar) << 10) + ((n & 7) << 7)
                      + ((((k & 63) << 1)) ^ ((n & 7) << 4)));
}

// ================= prep: fold + split + swizzle weights =================
__global__ void prep_kernel(const float* __restrict__ W0, const float* __restrict__ W1) {
    int gid = blockIdx.x * blockDim.x + threadIdx.x;
    if (gid < 16384) {                 // B1: n=h, k=f -> Wcat[f][h]
        int n = gid >> 7, k = gid & 127;
        float v;
        if (k < 64) v = W0[(64 + k) * NH1 + n] - W0[(192 + k) * NH1 + n];
        else        v = W0[(128 + (k - 64)) * NH1 + n];
        __nv_bfloat16 h = __float2bfloat16(v);
        uint32_t off = boffB(n, k, 16);
        *(__nv_bfloat16*)((char*)&g_B1[0][0] + off) = h;
        *(__nv_bfloat16*)((char*)&g_B1[1][0] + off) =
            __float2bfloat16(v - __bfloat162float(h));
    } else if (gid < 24576) {          // B2: n=j, k=h -> W1[h][j]
        int i = gid - 16384;
        int n = i >> 7, k = i & 127;
        float v = W1[k * NH2 + n];
        __nv_bfloat16 h = __float2bfloat16(v);
        uint32_t off = boffB(n, k, 8);
        *(__nv_bfloat16*)((char*)&g_B2[0][0] + off) = h;
        *(__nv_bfloat16*)((char*)&g_B2[1][0] + off) =
            __float2bfloat16(v - __bfloat162float(h));
    } else if (gid < 32768) {          // Wq = W0a + W0d
        int i = gid - 24576;
        int e = i >> 7, hh = i & 127;
        g_Wq[e * NH1 + hh] = W0[e * NH1 + hh] + W0[(192 + e) * NH1 + hh];
    }
}

// ====== persistent fused kernel: two independent 448-thread halves ======
__global__ __launch_bounds__(NTHREADS, 1)
void din_kernel(const float* __restrict__ q_g,
                const float* __restrict__ keys_g,
                const int*   __restrict__ klen_g,
                const float* __restrict__ b0_g,
                const float* __restrict__ b1_g,
                const float* __restrict__ W2_g,
                const float* __restrict__ b2_g,
                float* __restrict__ out_g,
                float* __restrict__ attn_g) {
    extern __shared__ char smem[];
    const uint32_t sbase = smem_u32(smem);
    float* sW2  = (float*)(smem + OFF_W2);
    float* sB1b = (float*)(smem + OFF_B1B);

    const int t = threadIdx.x;
    const int half = t >= HALFT;          // 0 or 1
    const int tl = t - half * HALFT;      // 0..447 within half
    const int lane = tl & 31, wl = tl >> 5;   // 14 warps per half
    const int barid = half + 1;
    const float b2v = b2_g[0];

    // per-half pointers
    char* aB   = smem + OFF_A + half * A_HSZ;
    float* sC     = (float*)(smem + OFF_C     + half * 512);
    float* sScore = (float*)(smem + OFF_SCORE + half * 512);
    float* sPart  = (float*)(smem + OFF_PART  + half * 1024);
    float* sPOut  = (float*)(smem + OFF_POUT  + half * 512);

    // ---- weights -> smem ONCE (full CTA) ----
    {
        const uint4* s1 = &g_B1[0][0];
        uint4* d1 = (uint4*)(smem + OFF_B1);
        for (int i = t; i < 4096; i += NTHREADS) d1[i] = s1[i];
        const uint4* s2 = &g_B2[0][0];
        uint4* d2 = (uint4*)(smem + OFF_B2);
        for (int i = t; i < 2048; i += NTHREADS) d2[i] = s2[i];
        if (t < 64) { sW2[t] = W2_g[t]; sB1b[t] = b1_g[t]; }
    }
    // zero pad rows 100..111 of this half's A (both planes), once
    for (int i = tl; i < 12 * 64 * 2; i += HALFT) {
        int pl = i >= 12 * 64, r = (i % (12 * 64)) >> 6, kk = (i & 63) * 2;
        *(uint32_t*)(aB + pl * A_PLANE + boffA(100 + r, kk)) = 0u;
    }
    __syncthreads();

    // ---- lane geometry (per half; M-tile 112, warp tile m16) ----
    const int mg = wl >> 1, ng = wl & 1;
    const int s0 = mg * 16;                    // warp row base (0..96)
    const int rA = s0 + (lane & 15);
    const uint32_t aBase = sbase + OFF_A + half * A_HSZ
                         + ((rA >> 3) << 10) + ((rA & 7) << 7);
    const uint32_t hsxA = (((lane >> 4) & 1) * 16) ^ ((lane & 7) << 4);
    const uint32_t hsxB = (((lane >> 3) & 1) * 16) ^ ((lane & 7) << 4);
    const int h0 = ng * 64, j0 = ng * 32;
    const uint32_t b1Base = sbase + OFF_B1 + (((h0 >> 3) + ((lane >> 4) & 1)) << 10)
                          + ((lane & 7) << 7);
    const uint32_t b2Base = sbase + OFF_B2 + (((j0 >> 3) + ((lane >> 4) & 1)) << 10)
                          + ((lane & 7) << 7);

    const int bstep = gridDim.x * 2;
    for (long b = blockIdx.x * 2 + half; b < NB; b += bstep) {

        // ---- build Kp (rows 0..99) ----
        for (int i = tl; i < 3200; i += HALFT) {
            int s = i >> 5, pp = i & 31;
            float2 kv = *(const float2*)&keys_g[(b * NS + s) * NE + 2 * pp];
            float2 qv = *(const float2*)&q_g[b * NE + 2 * pp];
            uint32_t hi, lo;
            split_pair(kv.x, kv.y, hi, lo);
            uint32_t o = boffA(s, 2 * pp);
            *(uint32_t*)(aB + o) = hi;
            *(uint32_t*)(aB + A_PLANE + o) = lo;
            split_pair(kv.x * qv.x, kv.y * qv.y, hi, lo);
            o = boffA(s, 64 + 2 * pp);
            *(uint32_t*)(aB + o) = hi;
            *(uint32_t*)(aB + A_PLANE + o) = lo;
        }
        // ---- c[h] = b0[h] + q . Wq[:,h] ----
        if (tl < 128) {
            const float* qb = q_g + b * NE;
            float acc0 = b0_g[tl];
            #pragma unroll 8
            for (int e = 0; e < NE; e++) acc0 = fmaf(qb[e], g_Wq[e * NH1 + tl], acc0);
            sC[tl] = acc0;
        }
        barh(barid);

        // ================= GEMM1: D1[112 x 128] = Kp @ Wcat =================
        float acc[8][4];
        #pragma unroll
        for (int i = 0; i < 8; i++)
            #pragma unroll
            for (int j = 0; j < 4; j++) acc[i][j] = 0.f;

        #pragma unroll
        for (int k = 0; k < 8; k++) {
            const uint32_t kbA = ((k < 4) ? k * 32u : 14336u + (k - 4) * 32u) ^ hsxA;
            const uint32_t kbB = ((k < 4) ? k * 32u : 16384u + (k - 4) * 32u) ^ hsxB;
            uint32_t ah0[4], al0[4];
            ldsm4(ah0, aBase + kbA);
            ldsm4(al0, aBase + A_PLANE + kbA);
            #pragma unroll
            for (int np = 0; np < 4; np++) {
                uint32_t bh[4], bl[4];
                const uint32_t ab = b1Base + np * 2048 + kbB;
                ldsm4(bh, ab);
                ldsm4(bl, ab + B1_HALF);
                const int nt = np * 2;
                mma_bf16(acc[nt],     ah0, bh[0], bh[1]);
                mma_bf16(acc[nt + 1], ah0, bh[2], bh[3]);
                mma_bf16(acc[nt],     ah0, bl[0], bl[1]);
                mma_bf16(acc[nt + 1], ah0, bl[2], bl[3]);
                mma_bf16(acc[nt],     al0, bh[0], bh[1]);
                mma_bf16(acc[nt + 1], al0, bh[2], bh[3]);
            }
        }
        barh(barid);   // all A reads done

        // ---- epilogue1: H0 = relu(D1 + c) -> split -> A region ----
        {
            const int row = s0 + (lane >> 2);
            #pragma unroll
            for (int nt = 0; nt < 8; nt++) {
                const float* c = acc[nt];
                const int col = h0 + nt * 8 + (lane & 3) * 2;
                const float c0 = sC[col], c1 = sC[col + 1];
                uint32_t hi, lo, o;
                split_pair(fmaxf(c[0] + c0, 0.f), fmaxf(c[1] + c1, 0.f), hi, lo);
                o = boffA(row, col);
                *(uint32_t*)(aB + o) = hi;
                *(uint32_t*)(aB + A_PLANE + o) = lo;
                split_pair(fmaxf(c[2] + c0, 0.f), fmaxf(c[3] + c1, 0.f), hi, lo);
                o = boffA(row + 8, col);
                *(uint32_t*)(aB + o) = hi;
                *(uint32_t*)(aB + A_PLANE + o) = lo;
            }
        }
        barh(barid);

        // ================= GEMM2: D2[112 x 64] = H0 @ W1 =================
        float acc2[4][4];
        #pragma unroll
        for (int i = 0; i < 4; i++)
            #pragma unroll
            for (int j = 0; j < 4; j++) acc2[i][j] = 0.f;

        #pragma unroll
        for (int k = 0; k < 8; k++) {
            const uint32_t kbA = ((k < 4) ? k * 32u : 14336u + (k - 4) * 32u) ^ hsxA;
            const uint32_t kbB = ((k < 4) ? k * 32u : 8192u + (k - 4) * 32u) ^ hsxB;
            uint32_t ah0[4], al0[4];
            ldsm4(ah0, aBase + kbA);
            ldsm4(al0, aBase + A_PLANE + kbA);
            #pragma unroll
            for (int np = 0; np < 2; np++) {
                uint32_t bh[4], bl[4];
                const uint32_t ab = b2Base + np * 2048 + kbB;
                ldsm4(bh, ab);
                ldsm4(bl, ab + B2_HALF);
                const int nt = np * 2;
                mma_bf16(acc2[nt],     ah0, bh[0], bh[1]);
                mma_bf16(acc2[nt + 1], ah0, bh[2], bh[3]);
                mma_bf16(acc2[nt],     ah0, bl[0], bl[1]);
                mma_bf16(acc2[nt + 1], ah0, bl[2], bl[3]);
                mma_bf16(acc2[nt],     al0, bh[0], bh[1]);
                mma_bf16(acc2[nt + 1], al0, bh[2], bh[3]);
            }
        }

        // ---- epilogue2: partial scores -> sPart ----
        {
            float part[2] = {0.f, 0.f};
            #pragma unroll
            for (int nt = 0; nt < 4; nt++) {
                const float* c = acc2[nt];
                const int col = j0 + nt * 8 + (lane & 3) * 2;
                const float bb0 = sB1b[col], bb1 = sB1b[col + 1];
                const float w0v = sW2[col], w1v = sW2[col + 1];
                part[0] += fmaxf(c[0] + bb0, 0.f) * w0v + fmaxf(c[1] + bb1, 0.f) * w1v;
                part[1] += fmaxf(c[2] + bb0, 0.f) * w0v + fmaxf(c[3] + bb1, 0.f) * w1v;
            }
            #pragma unroll
            for (int i = 0; i < 2; i++) {
                float v = part[i];
                v += __shfl_xor_sync(0xffffffffu, v, 1);
                v += __shfl_xor_sync(0xffffffffu, v, 2);
                if ((lane & 3) == 0) {
                    const int row = s0 + (lane >> 2) + i * 8;
                    sPart[row * 2 + ng] = v;
                }
            }
        }
        barh(barid);

        // ---- masked softmax + attn store (warp 0 of half) ----
        if (wl == 0) {
            const int len = klen_g[b];
            float m = -1e30f;
            float sv[4];
            #pragma unroll
            for (int i = 0; i < 4; i++) {
                int s = lane + i * 32;
                float v = -1e30f;
                if (s < NS) {
                    v = sPart[s * 2] + sPart[s * 2 + 1] + b2v;
                    if (s >= len) v = -1e30f;
                }
                sv[i] = v;
                m = fmaxf(m, v);
            }
            #pragma unroll
            for (int off = 16; off; off >>= 1)
                m = fmaxf(m, __shfl_xor_sync(0xffffffffu, m, off));
            float sum = 0.f;
            #pragma unroll
            for (int i = 0; i < 4; i++) {
                int s = lane + i * 32;
                float v = (s < len) ? expf(sv[i] - m) : 0.f;
                sv[i] = v;
                sum += v;
            }
            #pragma unroll
            for (int off = 16; off; off >>= 1)
                sum += __shfl_xor_sync(0xffffffffu, sum, off);
            float inv = 1.f / sum;
            #pragma unroll
            for (int i = 0; i < 4; i++) {
                int s = lane + i * 32;
                if (s < NS) {
                    float a = sv[i] * inv;
                    sScore[s] = a;
                    if (attn_g) attn_g[b * NS + s] = a;
                }
            }
        }
        barh(barid);

        // ---- out[e] = sum_s attn[s] * keys[s][e] ----
        if (tl < 128) {
            const int g = tl >> 6, e = tl & 63;
            const float* kb = keys_g + b * NS * NE;
            float a = 0.f;
            for (int s = g; s < NS; s += 2) a = fmaf(sScore[s], kb[s * NE + e], a);
            sPOut[g * 64 + e] = a;
        }
        barh(barid);
        if (tl < 64) out_g[b * NE + tl] = sPOut[tl] + sPOut[64 + tl];
        // next iteration's first write (A/sC) is barrier-separated from all
        // remaining readers via the barh chain above.
        barh(barid);
    }
}

extern "C" void kernel_launch(void* const* d_in, const int* in_sizes, int n_in,
                              void* d_out, int out_size) {
    const float* query = (const float*)d_in[0];
    const float* keys  = (const float*)d_in[1];
    const int*   klen  = (const int*)  d_in[2];
    const float* W0    = (const float*)d_in[3];
    const float* b0    = (const float*)d_in[4];
    const float* W1    = (const float*)d_in[5];
    const float* b1    = (const float*)d_in[6];
    const float* W2    = (const float*)d_in[7];
    const float* b2    = (const float*)d_in[8];

    float* outp  = (float*)d_out;
    float* attnp = (out_size >= NB * NE + NB * NS) ? outp + (size_t)NB * NE : nullptr;

    int dev = 0, nsm = 148;
    cudaGetDevice(&dev);
    cudaDeviceGetAttribute(&nsm, cudaDevAttrMultiProcessorCount, dev);

    cudaFuncSetAttribute(din_kernel, cudaFuncAttributeMaxDynamicSharedMemorySize, SMEM_TOTAL);

    prep_kernel<<<64, 512>>>(W0, W1);
    din_kernel<<<nsm, NTHREADS, SMEM_TOTAL>>>(query, keys, klen, b0, b1, W2, b2,
                                              outp, attnp);
}

// round 14
// speedup vs baseline: 2.1180x; 1.0660x over previous
#include <cuda_runtime.h>
#include <cuda_fp16.h>
#include <cstdint>

#define NB   8192
#define NS   100
#define NE   64
#define NH1  128
#define NH2  64
#define NTHREADS 896   // 2 halves x 448 threads (14 warps each)
#define HALFT 448

// ---- smem layout (bytes) ----
// Per-half A: [112 rows x 128k] fp16 single plane, swizzled nar=14: 28672 B
#define OFF_A     0
#define A_HSZ     28672             // per-half A block
#define OFF_B1    57344             // B1 hi (32768) + lo (32768)
#define B1_HALF   32768
#define OFF_B2    122880            // B2 hi (16384) + lo (16384)
#define B2_HALF   16384
#define OFF_W2    155648            // W2[64] f32
#define OFF_B1B   155904            // b1[64] f32
#define OFF_C     156160            // per-half c[128] f32 (2 x 512)
#define OFF_SCORE 157184            // per-half scores[128] f32 (2 x 512)
#define OFF_PART  158208            // per-half score partials [112][2] f32 (2 x 1024)
#define OFF_POUT  160256            // per-half out partials [2][64] f32 (2 x 512)
#define SMEM_TOTAL 161280

// ---- device scratch: pre-split, pre-swizzled fp16 weights ----
__device__ uint4 g_B1[2][2048];   // hi/lo 32KB each, [128n][128k] swizzled nar=16
__device__ uint4 g_B2[2][1024];   // hi/lo 16KB each, [64n][128k]  swizzled nar=8
__device__ float g_Wq[NE * NH1];  // [e][h] = W0a + W0d

// ================= helpers =================
__device__ __forceinline__ uint32_t smem_u32(const void* p) {
    uint32_t a;
    asm("{ .reg .u64 t; cvta.to.shared.u64 t, %1; cvt.u32.u64 %0, t; }" : "=r"(a) : "l"(p));
    return a;
}
__device__ __forceinline__ void barh(int id) {
    asm volatile("bar.sync %0, %1;" :: "r"(id), "r"(HALFT) : "memory");
}
__device__ __forceinline__ void ldsm4(uint32_t* r, uint32_t addr) {
    asm volatile("ldmatrix.sync.aligned.m8n8.x4.shared.b16 {%0,%1,%2,%3}, [%4];"
                 : "=r"(r[0]), "=r"(r[1]), "=r"(r[2]), "=r"(r[3]) : "r"(addr));
}
__device__ __forceinline__ void mma_f16(float* c, const uint32_t* a, uint32_t b0, uint32_t b1) {
    asm volatile("mma.sync.aligned.m16n8k16.row.col.f32.f16.f16.f32 "
                 "{%0,%1,%2,%3}, {%4,%5,%6,%7}, {%8,%9}, {%0,%1,%2,%3};"
                 : "+f"(c[0]), "+f"(c[1]), "+f"(c[2]), "+f"(c[3])
                 : "r"(a[0]), "r"(a[1]), "r"(a[2]), "r"(a[3]), "r"(b0), "r"(b1));
}
// pack two f32 -> f16x2 (x0 -> low half, x1 -> high half)
__device__ __forceinline__ uint32_t cvt_f16x2(float x0, float x1) {
    uint32_t r;
    asm("cvt.rn.f16x2.f32 %0, %1, %2;" : "=r"(r) : "f"(x1), "f"(x0));
    return r;
}
// swizzled byte offset in per-half A (nar=14): row 0..111, k elem 0..127
__device__ __forceinline__ uint32_t boffA(int row, int k) {
    return (uint32_t)((((row >> 3) + (k >> 6) * 14) << 10) + ((row & 7) << 7)
                      + ((((k & 63) << 1)) ^ ((row & 7) << 4)));
}
// generic swizzled offset for prep (nar = rows/8)
__device__ __forceinline__ uint32_t boffB(int n, int k, int nar) {
    return (uint32_t)((((n >> 3) + (k >> 6) * nar) << 10) + ((n & 7) << 7)
                      + ((((k & 63) << 1)) ^ ((n & 7) << 4)));
}

// ================= prep: fold + split(fp16) + swizzle weights =================
__global__ void prep_kernel(const float* __restrict__ W0, const float* __restrict__ W1) {
    int gid = blockIdx.x * blockDim.x + threadIdx.x;
    if (gid < 16384) {                 // B1: n=h, k=f -> Wcat[f][h]
        int n = gid >> 7, k = gid & 127;
        float v;
        if (k < 64) v = W0[(64 + k) * NH1 + n] - W0[(192 + k) * NH1 + n];
        else        v = W0[(128 + (k - 64)) * NH1 + n];
        __half h = __float2half_rn(v);
        __half l = __float2half_rn(v - __half2float(h));
        uint32_t off = boffB(n, k, 16);
        *(__half*)((char*)&g_B1[0][0] + off) = h;
        *(__half*)((char*)&g_B1[1][0] + off) = l;
    } else if (gid < 24576) {          // B2: n=j, k=h -> W1[h][j]
        int i = gid - 16384;
        int n = i >> 7, k = i & 127;
        float v = W1[k * NH2 + n];
        __half h = __float2half_rn(v);
        __half l = __float2half_rn(v - __half2float(h));
        uint32_t off = boffB(n, k, 8);
        *(__half*)((char*)&g_B2[0][0] + off) = h;
        *(__half*)((char*)&g_B2[1][0] + off) = l;
    } else if (gid < 32768) {          // Wq = W0a + W0d
        int i = gid - 24576;
        int e = i >> 7, hh = i & 127;
        g_Wq[e * NH1 + hh] = W0[e * NH1 + hh] + W0[(192 + e) * NH1 + hh];
    }
}

// ====== persistent fused kernel: two independent 448-thread halves ======
__global__ __launch_bounds__(NTHREADS, 1)
void din_kernel(const float* __restrict__ q_g,
                const float* __restrict__ keys_g,
                const int*   __restrict__ klen_g,
                const float* __restrict__ b0_g,
                const float* __restrict__ b1_g,
                const float* __restrict__ W2_g,
                const float* __restrict__ b2_g,
                float* __restrict__ out_g,
                float* __restrict__ attn_g) {
    extern __shared__ char smem[];
    const uint32_t sbase = smem_u32(smem);
    float* sW2  = (float*)(smem + OFF_W2);
    float* sB1b = (float*)(smem + OFF_B1B);

    const int t = threadIdx.x;
    const int half = t >= HALFT;          // 0 or 1
    const int tl = t - half * HALFT;      // 0..447 within half
    const int lane = tl & 31, wl = tl >> 5;   // 14 warps per half
    const int barid = half + 1;
    const float b2v = b2_g[0];

    // per-half pointers
    char* aB      = smem + OFF_A + half * A_HSZ;
    float* sC     = (float*)(smem + OFF_C     + half * 512);
    float* sScore = (float*)(smem + OFF_SCORE + half * 512);
    float* sPart  = (float*)(smem + OFF_PART  + half * 1024);
    float* sPOut  = (float*)(smem + OFF_POUT  + half * 512);

    // ---- weights -> smem ONCE (full CTA) ----
    {
        const uint4* s1 = &g_B1[0][0];
        uint4* d1 = (uint4*)(smem + OFF_B1);
        for (int i = t; i < 4096; i += NTHREADS) d1[i] = s1[i];
        const uint4* s2 = &g_B2[0][0];
        uint4* d2 = (uint4*)(smem + OFF_B2);
        for (int i = t; i < 2048; i += NTHREADS) d2[i] = s2[i];
        if (t < 64) { sW2[t] = W2_g[t]; sB1b[t] = b1_g[t]; }
    }
    // zero pad rows 100..111 of this half's A, once
    for (int i = tl; i < 12 * 64; i += HALFT) {
        int r = i >> 6, kk = (i & 63) * 2;
        *(uint32_t*)(aB + boffA(100 + r, kk)) = 0u;
    }
    __syncthreads();

    // ---- lane geometry (per half; M-tile 112, warp tile m16) ----
    const int mg = wl >> 1, ng = wl & 1;
    const int s0 = mg * 16;                    // warp row base (0..96)
    const int rA = s0 + (lane & 15);
    const uint32_t aBase = sbase + OFF_A + half * A_HSZ
                         + ((rA >> 3) << 10) + ((rA & 7) << 7);
    const uint32_t hsxA = (((lane >> 4) & 1) * 16) ^ ((lane & 7) << 4);
    const uint32_t hsxB = (((lane >> 3) & 1) * 16) ^ ((lane & 7) << 4);
    const int h0 = ng * 64, j0 = ng * 32;
    const uint32_t b1Base = sbase + OFF_B1 + (((h0 >> 3) + ((lane >> 4) & 1)) << 10)
                          + ((lane & 7) << 7);
    const uint32_t b2Base = sbase + OFF_B2 + (((j0 >> 3) + ((lane >> 4) & 1)) << 10)
                          + ((lane & 7) << 7);

    const int bstep = gridDim.x * 2;
    for (long b = blockIdx.x * 2 + half; b < NB; b += bstep) {

        // ---- build Kp (rows 0..99), single fp16 plane ----
        for (int i = tl; i < 3200; i += HALFT) {
            int s = i >> 5, pp = i & 31;
            float2 kv = *(const float2*)&keys_g[(b * NS + s) * NE + 2 * pp];
            float2 qv = *(const float2*)&q_g[b * NE + 2 * pp];
            *(uint32_t*)(aB + boffA(s, 2 * pp)) = cvt_f16x2(kv.x, kv.y);
            *(uint32_t*)(aB + boffA(s, 64 + 2 * pp)) =
                cvt_f16x2(kv.x * qv.x, kv.y * qv.y);
        }
        // ---- c[h] = b0[h] + q . Wq[:,h] ----
        if (tl < 128) {
            const float* qb = q_g + b * NE;
            float acc0 = b0_g[tl];
            #pragma unroll 8
            for (int e = 0; e < NE; e++) acc0 = fmaf(qb[e], g_Wq[e * NH1 + tl], acc0);
            sC[tl] = acc0;
        }
        barh(barid);

        // ================= GEMM1: D1[112 x 128] = Kp @ Wcat =================
        float acc[8][4];
        #pragma unroll
        for (int i = 0; i < 8; i++)
            #pragma unroll
            for (int j = 0; j < 4; j++) acc[i][j] = 0.f;

        #pragma unroll
        for (int k = 0; k < 8; k++) {
            const uint32_t kbA = ((k < 4) ? k * 32u : 14336u + (k - 4) * 32u) ^ hsxA;
            const uint32_t kbB = ((k < 4) ? k * 32u : 16384u + (k - 4) * 32u) ^ hsxB;
            uint32_t ah0[4];
            ldsm4(ah0, aBase + kbA);
            #pragma unroll
            for (int np = 0; np < 4; np++) {
                uint32_t bh[4], bl[4];
                const uint32_t ab = b1Base + np * 2048 + kbB;
                ldsm4(bh, ab);
                ldsm4(bl, ab + B1_HALF);
                const int nt = np * 2;
                mma_f16(acc[nt],     ah0, bh[0], bh[1]);
                mma_f16(acc[nt + 1], ah0, bh[2], bh[3]);
                mma_f16(acc[nt],     ah0, bl[0], bl[1]);
                mma_f16(acc[nt + 1], ah0, bl[2], bl[3]);
            }
        }
        barh(barid);   // all A reads done

        // ---- epilogue1: H0 = relu(D1 + c) -> fp16 -> A region ----
        {
            const int row = s0 + (lane >> 2);
            #pragma unroll
            for (int nt = 0; nt < 8; nt++) {
                const float* c = acc[nt];
                const int col = h0 + nt * 8 + (lane & 3) * 2;
                const float c0 = sC[col], c1 = sC[col + 1];
                *(uint32_t*)(aB + boffA(row, col)) =
                    cvt_f16x2(fmaxf(c[0] + c0, 0.f), fmaxf(c[1] + c1, 0.f));
                *(uint32_t*)(aB + boffA(row + 8, col)) =
                    cvt_f16x2(fmaxf(c[2] + c0, 0.f), fmaxf(c[3] + c1, 0.f));
            }
        }
        barh(barid);

        // ================= GEMM2: D2[112 x 64] = H0 @ W1 =================
        float acc2[4][4];
        #pragma unroll
        for (int i = 0; i < 4; i++)
            #pragma unroll
            for (int j = 0; j < 4; j++) acc2[i][j] = 0.f;

        #pragma unroll
        for (int k = 0; k < 8; k++) {
            const uint32_t kbA = ((k < 4) ? k * 32u : 14336u + (k - 4) * 32u) ^ hsxA;
            const uint32_t kbB = ((k < 4) ? k * 32u : 8192u + (k - 4) * 32u) ^ hsxB;
            uint32_t ah0[4];
            ldsm4(ah0, aBase + kbA);
            #pragma unroll
            for (int np = 0; np < 2; np++) {
                uint32_t bh[4], bl[4];
                const uint32_t ab = b2Base + np * 2048 + kbB;
                ldsm4(bh, ab);
                ldsm4(bl, ab + B2_HALF);
                const int nt = np * 2;
                mma_f16(acc2[nt],     ah0, bh[0], bh[1]);
                mma_f16(acc2[nt + 1], ah0, bh[2], bh[3]);
                mma_f16(acc2[nt],     ah0, bl[0], bl[1]);
                mma_f16(acc2[nt + 1], ah0, bl[2], bl[3]);
            }
        }

        // ---- epilogue2: partial scores -> sPart ----
        {
            float part[2] = {0.f, 0.f};
            #pragma unroll
            for (int nt = 0; nt < 4; nt++) {
                const float* c = acc2[nt];
                const int col = j0 + nt * 8 + (lane & 3) * 2;
                const float bb0 = sB1b[col], bb1 = sB1b[col + 1];
                const float w0v = sW2[col], w1v = sW2[col + 1];
                part[0] += fmaxf(c[0] + bb0, 0.f) * w0v + fmaxf(c[1] + bb1, 0.f) * w1v;
                part[1] += fmaxf(c[2] + bb0, 0.f) * w0v + fmaxf(c[3] + bb1, 0.f) * w1v;
            }
            #pragma unroll
            for (int i = 0; i < 2; i++) {
                float v = part[i];
                v += __shfl_xor_sync(0xffffffffu, v, 1);
                v += __shfl_xor_sync(0xffffffffu, v, 2);
                if ((lane & 3) == 0) {
                    const int row = s0 + (lane >> 2) + i * 8;
                    sPart[row * 2 + ng] = v;
                }
            }
        }
        barh(barid);

        // ---- masked softmax + attn store (warp 0 of half) ----
        if (wl == 0) {
            const int len = klen_g[b];
            float m = -1e30f;
            float sv[4];
            #pragma unroll
            for (int i = 0; i < 4; i++) {
                int s = lane + i * 32;
                float v = -1e30f;
                if (s < NS) {
                    v = sPart[s * 2] + sPart[s * 2 + 1] + b2v;
                    if (s >= len) v = -1e30f;
                }
                sv[i] = v;
                m = fmaxf(m, v);
            }
            #pragma unroll
            for (int off = 16; off; off >>= 1)
                m = fmaxf(m, __shfl_xor_sync(0xffffffffu, m, off));
            float sum = 0.f;
            #pragma unroll
            for (int i = 0; i < 4; i++) {
                int s = lane + i * 32;
                float v = (s < len) ? expf(sv[i] - m) : 0.f;
                sv[i] = v;
                sum += v;
            }
            #pragma unroll
            for (int off = 16; off; off >>= 1)
                sum += __shfl_xor_sync(0xffffffffu, sum, off);
            float inv = 1.f / sum;
            #pragma unroll
            for (int i = 0; i < 4; i++) {
                int s = lane + i * 32;
                if (s < NS) {
                    float a = sv[i] * inv;
                    sScore[s] = a;
                    if (attn_g) attn_g[b * NS + s] = a;
                }
            }
        }
        barh(barid);

        // ---- out[e] = sum_s attn[s] * keys[s][e] ----
        if (tl < 128) {
            const int g = tl >> 6, e = tl & 63;
            const float* kb = keys_g + b * NS * NE;
            float a = 0.f;
            for (int s = g; s < NS; s += 2) a = fmaf(sScore[s], kb[s * NE + e], a);
            sPOut[g * 64 + e] = a;
        }
        barh(barid);
        if (tl < 64) out_g[b * NE + tl] = sPOut[tl] + sPOut[64 + tl];
        barh(barid);
    }
}

extern "C" void kernel_launch(void* const* d_in, const int* in_sizes, int n_in,
                              void* d_out, int out_size) {
    const float* query = (const float*)d_in[0];
    const float* keys  = (const float*)d_in[1];
    const int*   klen  = (const int*)  d_in[2];
    const float* W0    = (const float*)d_in[3];
    const float* b0    = (const float*)d_in[4];
    const float* W1    = (const float*)d_in[5];
    const float* b1    = (const float*)d_in[6];
    const float* W2    = (const float*)d_in[7];
    const float* b2    = (const float*)d_in[8];

    float* outp  = (float*)d_out;
    float* attnp = (out_size >= NB * NE + NB * NS) ? outp + (size_t)NB * NE : nullptr;

    int dev = 0, nsm = 148;
    cudaGetDevice(&dev);
    cudaDeviceGetAttribute(&nsm, cudaDevAttrMultiProcessorCount, dev);

    cudaFuncSetAttribute(din_kernel, cudaFuncAttributeMaxDynamicSharedMemorySize, SMEM_TOTAL);

    prep_kernel<<<64, 512>>>(W0, W1);
    din_kernel<<<nsm, NTHREADS, SMEM_TOTAL>>>(query, keys, klen, b0, b1, W2, b2,
                                              outp, attnp);
}

// round 15
// speedup vs baseline: 2.5392x; 1.1989x over previous
#include <cuda_runtime.h>
#include <cuda_fp16.h>
#include <cstdint>

#define NB   8192
#define NS   100
#define NE   64
#define NH1  128
#define NH2  64
#define NTHREADS 896   // 28 warps: 7 m-groups (32 rows) x 4 n-groups, M-tile 224

// ---- smem layout (bytes) ----
#define OFF_A     0                 // A [224 rows x 128k] fp16, swizzled nar=28
#define OFF_B1    57344             // B1 hi (32768) + lo (32768)
#define B1_HALF   32768
#define OFF_B2    122880            // B2 hi (16384) + lo (16384)
#define B2_HALF   16384
#define OFF_W2    155648            // W2[64] f32
#define OFF_B1B   155904            // b1[64] f32
#define OFF_C     156160            // c[2][128] f32
#define OFF_SCORE 157184            // attn scores [2][128] f32
#define OFF_PART  158208            // score partials [224][4] f32
#define OFF_POUT  161792            // out partials [2][2][64] f32
#define SMEM_TOTAL 162816

// ---- device scratch: pre-split, pre-swizzled fp16 weights ----
__device__ uint4 g_B1[2][2048];   // hi/lo 32KB each, [128n][128k] swizzled nar=16
__device__ uint4 g_B2[2][1024];   // hi/lo 16KB each, [64n][128k]  swizzled nar=8
__device__ float g_Wq[NE * NH1];  // [e][h] = W0a + W0d

// ================= helpers =================
__device__ __forceinline__ uint32_t smem_u32(const void* p) {
    uint32_t a;
    asm("{ .reg .u64 t; cvta.to.shared.u64 t, %1; cvt.u32.u64 %0, t; }" : "=r"(a) : "l"(p));
    return a;
}
__device__ __forceinline__ void ldsm4(uint32_t* r, uint32_t addr) {
    asm volatile("ldmatrix.sync.aligned.m8n8.x4.shared.b16 {%0,%1,%2,%3}, [%4];"
                 : "=r"(r[0]), "=r"(r[1]), "=r"(r[2]), "=r"(r[3]) : "r"(addr));
}
__device__ __forceinline__ void mma_f16(float* c, const uint32_t* a, uint32_t b0, uint32_t b1) {
    asm volatile("mma.sync.aligned.m16n8k16.row.col.f32.f16.f16.f32 "
                 "{%0,%1,%2,%3}, {%4,%5,%6,%7}, {%8,%9}, {%0,%1,%2,%3};"
                 : "+f"(c[0]), "+f"(c[1]), "+f"(c[2]), "+f"(c[3])
                 : "r"(a[0]), "r"(a[1]), "r"(a[2]), "r"(a[3]), "r"(b0), "r"(b1));
}
// pack two f32 -> f16x2 (x0 -> low half, x1 -> high half)
__device__ __forceinline__ uint32_t cvt_f16x2(float x0, float x1) {
    uint32_t r;
    asm("cvt.rn.f16x2.f32 %0, %1, %2;" : "=r"(r) : "f"(x1), "f"(x0));
    return r;
}
// swizzled byte offset in A (nar=28): row 0..223, k elem 0..127
__device__ __forceinline__ uint32_t boffA(int row, int k) {
    return (uint32_t)((((row >> 3) + (k >> 6) * 28) << 10) + ((row & 7) << 7)
                      + ((((k & 63) << 1)) ^ ((row & 7) << 4)));
}
// generic swizzled offset for prep (nar = rows/8)
__device__ __forceinline__ uint32_t boffB(int n, int k, int nar) {
    return (uint32_t)((((n >> 3) + (k >> 6) * nar) << 10) + ((n & 7) << 7)
                      + ((((k & 63) << 1)) ^ ((n & 7) << 4)));
}

// ================= prep: fold + split(fp16) + swizzle weights =================
__global__ void prep_kernel(const float* __restrict__ W0, const float* __restrict__ W1) {
    int gid = blockIdx.x * blockDim.x + threadIdx.x;
    if (gid < 16384) {                 // B1: n=h, k=f -> Wcat[f][h]
        int n = gid >> 7, k = gid & 127;
        float v;
        if (k < 64) v = W0[(64 + k) * NH1 + n] - W0[(192 + k) * NH1 + n];
        else        v = W0[(128 + (k - 64)) * NH1 + n];
        __half h = __float2half_rn(v);
        __half l = __float2half_rn(v - __half2float(h));
        uint32_t off = boffB(n, k, 16);
        *(__half*)((char*)&g_B1[0][0] + off) = h;
        *(__half*)((char*)&g_B1[1][0] + off) = l;
    } else if (gid < 24576) {          // B2: n=j, k=h -> W1[h][j]
        int i = gid - 16384;
        int n = i >> 7, k = i & 127;
        float v = W1[k * NH2 + n];
        __half h = __float2half_rn(v);
        __half l = __float2half_rn(v - __half2float(h));
        uint32_t off = boffB(n, k, 8);
        *(__half*)((char*)&g_B2[0][0] + off) = h;
        *(__half*)((char*)&g_B2[1][0] + off) = l;
    } else if (gid < 32768) {          // Wq = W0a + W0d
        int i = gid - 24576;
        int e = i >> 7, hh = i & 127;
        g_Wq[e * NH1 + hh] = W0[e * NH1 + hh] + W0[(192 + e) * NH1 + hh];
    }
}

// ====== persistent fused kernel: 896 threads, m32 warp tiles, 2 batches/iter ======
__global__ __launch_bounds__(NTHREADS, 1)
void din_kernel(const float* __restrict__ q_g,
                const float* __restrict__ keys_g,
                const int*   __restrict__ klen_g,
                const float* __restrict__ b0_g,
                const float* __restrict__ b1_g,
                const float* __restrict__ W2_g,
                const float* __restrict__ b2_g,
                float* __restrict__ out_g,
                float* __restrict__ attn_g,
                int npairs) {
    extern __shared__ char smem[];
    const uint32_t sbase = smem_u32(smem);
    float* sW2    = (float*)(smem + OFF_W2);
    float* sB1b   = (float*)(smem + OFF_B1B);
    float* sC     = (float*)(smem + OFF_C);
    float* sScore = (float*)(smem + OFF_SCORE);
    float* sPart  = (float*)(smem + OFF_PART);
    float* sPOut  = (float*)(smem + OFF_POUT);

    const int t = threadIdx.x;
    const int lane = t & 31, w = t >> 5;
    const float b2v = b2_g[0];

    // ---- weights -> smem ONCE ----
    {
        const uint4* s1 = &g_B1[0][0];
        uint4* d1 = (uint4*)(smem + OFF_B1);
        for (int i = t; i < 4096; i += NTHREADS) d1[i] = s1[i];
        const uint4* s2 = &g_B2[0][0];
        uint4* d2 = (uint4*)(smem + OFF_B2);
        for (int i = t; i < 2048; i += NTHREADS) d2[i] = s2[i];
        if (t < 64) { sW2[t] = W2_g[t]; sB1b[t] = b1_g[t]; }
    }
    // zero pad rows 200..223, once
    for (int i = t; i < 24 * 64; i += NTHREADS) {
        int r = i >> 6, kk = (i & 63) * 2;
        *(uint32_t*)(smem + OFF_A + boffA(200 + r, kk)) = 0u;
    }
    __syncthreads();

    // ---- lane geometry: 7 m-groups (m32) x 4 n-groups ----
    const int mg = w >> 2, ng = w & 3;
    const int s0 = mg * 32;                    // warp row base (0..192)
    const int rA = s0 + (lane & 15);
    const uint32_t aBase = sbase + OFF_A + ((rA >> 3) << 10) + ((rA & 7) << 7);
    const uint32_t hsxA = (((lane >> 4) & 1) * 16) ^ ((lane & 7) << 4);
    const uint32_t hsxB = (((lane >> 3) & 1) * 16) ^ ((lane & 7) << 4);
    const int h0 = ng * 32;                    // GEMM1 n-range (32 wide)
    const int j0 = ng * 16;                    // GEMM2 n-range (16 wide)
    const uint32_t b1Base = sbase + OFF_B1 + (((h0 >> 3) + ((lane >> 4) & 1)) << 10)
                          + ((lane & 7) << 7);
    const uint32_t b2Base = sbase + OFF_B2 + (((j0 >> 3) + ((lane >> 4) & 1)) << 10)
                          + ((lane & 7) << 7);

    for (int p = blockIdx.x; p < npairs; p += gridDim.x) {
        const long gb0 = (long)p * 2;

        // ---- build Kp: batch0 -> rows 0..99, batch1 -> rows 100..199 ----
        for (int i = t; i < 3200; i += NTHREADS) {
            int batch = (i >= 1600), rem = i - batch * 1600;
            int s = rem >> 4, q = rem & 15;          // q: group of 4 k-elems
            int row = batch * 100 + s;
            float4 kv = *(const float4*)&keys_g[((gb0 + batch) * NS + s) * NE + 4 * q];
            float4 qv = *(const float4*)&q_g[(gb0 + batch) * NE + 4 * q];
            uint2 w0;
            w0.x = cvt_f16x2(kv.x, kv.y);
            w0.y = cvt_f16x2(kv.z, kv.w);
            *(uint2*)(smem + OFF_A + boffA(row, 4 * q)) = w0;
            uint2 w1;
            w1.x = cvt_f16x2(kv.x * qv.x, kv.y * qv.y);
            w1.y = cvt_f16x2(kv.z * qv.z, kv.w * qv.w);
            *(uint2*)(smem + OFF_A + boffA(row, 64 + 4 * q)) = w1;
        }
        // ---- c[batch][h] = b0[h] + q . Wq[:,h] ----
        if (t < 256) {
            int batch = t >> 7, h = t & 127;
            const float* qb = q_g + (gb0 + batch) * NE;
            float acc0 = b0_g[h];
            #pragma unroll 8
            for (int e = 0; e < NE; e++) acc0 = fmaf(qb[e], g_Wq[e * NH1 + h], acc0);
            sC[t] = acc0;
        }
        __syncthreads();

        // ================= GEMM1: D1[224 x 128] = Kp @ Wcat =================
        // warp tile m32 x n32
        float acc[8][4];   // [mt*4 + ntile]
        #pragma unroll
        for (int i = 0; i < 8; i++)
            #pragma unroll
            for (int j = 0; j < 4; j++) acc[i][j] = 0.f;

        #pragma unroll
        for (int k = 0; k < 8; k++) {
            const uint32_t kbA = ((k < 4) ? k * 32u : 28672u + (k - 4) * 32u) ^ hsxA;
            const uint32_t kbB = ((k < 4) ? k * 32u : 16384u + (k - 4) * 32u) ^ hsxB;
            uint32_t ah0[4], ah1[4];
            ldsm4(ah0, aBase + kbA);
            ldsm4(ah1, aBase + 2048 + kbA);
            #pragma unroll
            for (int np = 0; np < 2; np++) {
                uint32_t bh[4], bl[4];
                const uint32_t ab = b1Base + np * 2048 + kbB;
                ldsm4(bh, ab);
                ldsm4(bl, ab + B1_HALF);
                const int nt = np * 2;
                mma_f16(acc[nt],         ah0, bh[0], bh[1]);
                mma_f16(acc[nt + 1],     ah0, bh[2], bh[3]);
                mma_f16(acc[4 + nt],     ah1, bh[0], bh[1]);
                mma_f16(acc[4 + nt + 1], ah1, bh[2], bh[3]);
                mma_f16(acc[nt],         ah0, bl[0], bl[1]);
                mma_f16(acc[nt + 1],     ah0, bl[2], bl[3]);
                mma_f16(acc[4 + nt],     ah1, bl[0], bl[1]);
                mma_f16(acc[4 + nt + 1], ah1, bl[2], bl[3]);
            }
        }
        __syncthreads();   // all A reads done

        // ---- epilogue1: H0 = relu(D1 + c) -> fp16 -> A region ----
        #pragma unroll
        for (int mt = 0; mt < 2; mt++) {
            const int row = s0 + mt * 16 + (lane >> 2);
            const int cb0 = (row >= 100 ? 128 : 0);
            const int cb8 = (row + 8 >= 100 ? 128 : 0);
            #pragma unroll
            for (int nt = 0; nt < 4; nt++) {
                const float* c = acc[mt * 4 + nt];
                const int col = h0 + nt * 8 + (lane & 3) * 2;
                const float c0 = sC[cb0 + col], c1 = sC[cb0 + col + 1];
                const float d0 = sC[cb8 + col], d1 = sC[cb8 + col + 1];
                *(uint32_t*)(smem + OFF_A + boffA(row, col)) =
                    cvt_f16x2(fmaxf(c[0] + c0, 0.f), fmaxf(c[1] + c1, 0.f));
                *(uint32_t*)(smem + OFF_A + boffA(row + 8, col)) =
                    cvt_f16x2(fmaxf(c[2] + d0, 0.f), fmaxf(c[3] + d1, 0.f));
            }
        }
        __syncthreads();

        // ================= GEMM2: D2[224 x 64] = H0 @ W1 =================
        // warp tile m32 x n16
        float acc2[4][4];   // [mt*2 + nhalf]
        #pragma unroll
        for (int i = 0; i < 4; i++)
            #pragma unroll
            for (int j = 0; j < 4; j++) acc2[i][j] = 0.f;

        #pragma unroll
        for (int k = 0; k < 8; k++) {
            const uint32_t kbA = ((k < 4) ? k * 32u : 28672u + (k - 4) * 32u) ^ hsxA;
            const uint32_t kbB = ((k < 4) ? k * 32u : 8192u + (k - 4) * 32u) ^ hsxB;
            uint32_t ah0[4], ah1[4];
            ldsm4(ah0, aBase + kbA);
            ldsm4(ah1, aBase + 2048 + kbA);
            uint32_t bh[4], bl[4];
            const uint32_t ab = b2Base + kbB;
            ldsm4(bh, ab);
            ldsm4(bl, ab + B2_HALF);
            mma_f16(acc2[0], ah0, bh[0], bh[1]);
            mma_f16(acc2[1], ah0, bh[2], bh[3]);
            mma_f16(acc2[2], ah1, bh[0], bh[1]);
            mma_f16(acc2[3], ah1, bh[2], bh[3]);
            mma_f16(acc2[0], ah0, bl[0], bl[1]);
            mma_f16(acc2[1], ah0, bl[2], bl[3]);
            mma_f16(acc2[2], ah1, bl[0], bl[1]);
            mma_f16(acc2[3], ah1, bl[2], bl[3]);
        }

        // ---- epilogue2: partial scores -> sPart[row][ng] ----
        {
            float part[4] = {0.f, 0.f, 0.f, 0.f};   // [mt*2 + rowhalf]
            #pragma unroll
            for (int mt = 0; mt < 2; mt++) {
                #pragma unroll
                for (int nt = 0; nt < 2; nt++) {
                    const float* c = acc2[mt * 2 + nt];
                    const int col = j0 + nt * 8 + (lane & 3) * 2;
                    const float bb0 = sB1b[col], bb1 = sB1b[col + 1];
                    const float w0v = sW2[col], w1v = sW2[col + 1];
                    part[mt * 2]     += fmaxf(c[0] + bb0, 0.f) * w0v + fmaxf(c[1] + bb1, 0.f) * w1v;
                    part[mt * 2 + 1] += fmaxf(c[2] + bb0, 0.f) * w0v + fmaxf(c[3] + bb1, 0.f) * w1v;
                }
            }
            #pragma unroll
            for (int i = 0; i < 4; i++) {
                float v = part[i];
                v += __shfl_xor_sync(0xffffffffu, v, 1);
                v += __shfl_xor_sync(0xffffffffu, v, 2);
                if ((lane & 3) == 0) {
                    const int row = s0 + (i >> 1) * 16 + (lane >> 2) + (i & 1) * 8;
                    sPart[row * 4 + ng] = v;
                }
            }
        }
        __syncthreads();

        // ---- masked softmax + attn store: warp 0 -> batch0, warp 1 -> batch1 ----
        if (t < 64) {
            const int batch = t >> 5;
            float* sc = sScore + batch * 128;
            const float* pp = sPart + batch * 100 * 4;
            const int len = klen_g[gb0 + batch];
            float m = -1e30f;
            float sv[4];
            #pragma unroll
            for (int i = 0; i < 4; i++) {
                int s = lane + i * 32;
                float v = -1e30f;
                if (s < NS) {
                    v = pp[s * 4] + pp[s * 4 + 1] + pp[s * 4 + 2] + pp[s * 4 + 3] + b2v;
                    if (s >= len) v = -1e30f;
                }
                sv[i] = v;
                m = fmaxf(m, v);
            }
            #pragma unroll
            for (int off = 16; off; off >>= 1)
                m = fmaxf(m, __shfl_xor_sync(0xffffffffu, m, off));
            float sum = 0.f;
            #pragma unroll
            for (int i = 0; i < 4; i++) {
                int s = lane + i * 32;
                float v = (s < len) ? expf(sv[i] - m) : 0.f;
                sv[i] = v;
                sum += v;
            }
            #pragma unroll
            for (int off = 16; off; off >>= 1)
                sum += __shfl_xor_sync(0xffffffffu, sum, off);
            float inv = 1.f / sum;
            #pragma unroll
            for (int i = 0; i < 4; i++) {
                int s = lane + i * 32;
                if (s < NS) {
                    float a = sv[i] * inv;
                    sc[s] = a;
                    if (attn_g) attn_g[(gb0 + batch) * NS + s] = a;
                }
            }
        }
        __syncthreads();

        // ---- out[e] = sum_s attn[s] * keys[s][e] ----
        if (t < 256) {
            const int batch = t >> 7, rem = t & 127, g = rem >> 6, e = rem & 63;
            const float* kb = keys_g + (gb0 + batch) * NS * NE;
            const float* sc = sScore + batch * 128;
            float a = 0.f;
            for (int s = g; s < NS; s += 2) a = fmaf(sc[s], kb[s * NE + e], a);
            sPOut[batch * 128 + g * 64 + e] = a;
        }
        __syncthreads();
        if (t < 128) {
            const int batch = t >> 6, e = t & 63;
            out_g[(gb0 + batch) * NE + e] = sPOut[batch * 128 + e] + sPOut[batch * 128 + 64 + e];
        }
        // next iteration's first smem writes (A/sC) are separated from all
        // remaining readers by the barrier chain above.
    }
}

extern "C" void kernel_launch(void* const* d_in, const int* in_sizes, int n_in,
                              void* d_out, int out_size) {
    const float* query = (const float*)d_in[0];
    const float* keys  = (const float*)d_in[1];
    const int*   klen  = (const int*)  d_in[2];
    const float* W0    = (const float*)d_in[3];
    const float* b0    = (const float*)d_in[4];
    const float* W1    = (const float*)d_in[5];
    const float* b1    = (const float*)d_in[6];
    const float* W2    = (const float*)d_in[7];
    const float* b2    = (const float*)d_in[8];

    float* outp  = (float*)d_out;
    float* attnp = (out_size >= NB * NE + NB * NS) ? outp + (size_t)NB * NE : nullptr;

    int dev = 0, nsm = 148;
    cudaGetDevice(&dev);
    cudaDeviceGetAttribute(&nsm, cudaDevAttrMultiProcessorCount, dev);

    cudaFuncSetAttribute(din_kernel, cudaFuncAttributeMaxDynamicSharedMemorySize, SMEM_TOTAL);

    prep_kernel<<<64, 512>>>(W0, W1);
    din_kernel<<<nsm, NTHREADS, SMEM_TOTAL>>>(query, keys, klen, b0, b1, W2, b2,
                                              outp, attnp, NB / 2);
}

// round 16
// speedup vs baseline: 3.1017x; 1.2215x over previous
#include <cuda_runtime.h>
#include <cuda_fp16.h>
#include <cstdint>

#define NB   8192
#define NS   100
#define NE   64
#define NH1  128
#define NH2  64
#define NTHREADS 896   // 28 warps: 7 m-groups (32 rows) x 4 n-groups, M-tile 224

// ---- smem layout (bytes) ----
#define OFF_A     0                 // A [224 rows x 128k] fp16, swizzled nar=28 (57344)
#define OFF_B1    57344             // B1 fp16 single plane (32768)
#define OFF_B2    90112             // B2 fp16 single plane (16384)
#define OFF_W2    106496            // W2[64] f32
#define OFF_B1B   106752            // b1[64] f32
#define OFF_C     107008            // c[2][128] f32
#define OFF_SCORE 108032            // attn scores [2][128] f32
#define OFF_PART  109056            // score partials [224][4] f32 (3584)
#define OFF_POUT  112640            // out partials [2][2][64] f32 (1024)
#define SMEM_TOTAL 113664

// ---- device scratch: pre-folded, pre-swizzled fp16 weights (single plane) ----
__device__ uint4 g_B1[2048];      // 32KB, [128n][128k] swizzled nar=16
__device__ uint4 g_B2[1024];      // 16KB, [64n][128k]  swizzled nar=8
__device__ float g_Wq[NE * NH1];  // [e][h] = W0a + W0d

// ================= helpers =================
__device__ __forceinline__ uint32_t smem_u32(const void* p) {
    uint32_t a;
    asm("{ .reg .u64 t; cvta.to.shared.u64 t, %1; cvt.u32.u64 %0, t; }" : "=r"(a) : "l"(p));
    return a;
}
__device__ __forceinline__ void ldsm4(uint32_t* r, uint32_t addr) {
    asm volatile("ldmatrix.sync.aligned.m8n8.x4.shared.b16 {%0,%1,%2,%3}, [%4];"
                 : "=r"(r[0]), "=r"(r[1]), "=r"(r[2]), "=r"(r[3]) : "r"(addr));
}
__device__ __forceinline__ void mma_f16(float* c, const uint32_t* a, uint32_t b0, uint32_t b1) {
    asm volatile("mma.sync.aligned.m16n8k16.row.col.f32.f16.f16.f32 "
                 "{%0,%1,%2,%3}, {%4,%5,%6,%7}, {%8,%9}, {%0,%1,%2,%3};"
                 : "+f"(c[0]), "+f"(c[1]), "+f"(c[2]), "+f"(c[3])
                 : "r"(a[0]), "r"(a[1]), "r"(a[2]), "r"(a[3]), "r"(b0), "r"(b1));
}
// pack two f32 -> f16x2 (x0 -> low half, x1 -> high half)
__device__ __forceinline__ uint32_t cvt_f16x2(float x0, float x1) {
    uint32_t r;
    asm("cvt.rn.f16x2.f32 %0, %1, %2;" : "=r"(r) : "f"(x1), "f"(x0));
    return r;
}
// swizzled byte offset in A (nar=28): row 0..223, k elem 0..127
__device__ __forceinline__ uint32_t boffA(int row, int k) {
    return (uint32_t)((((row >> 3) + (k >> 6) * 28) << 10) + ((row & 7) << 7)
                      + ((((k & 63) << 1)) ^ ((row & 7) << 4)));
}
// generic swizzled offset for prep (nar = rows/8)
__device__ __forceinline__ uint32_t boffB(int n, int k, int nar) {
    return (uint32_t)((((n >> 3) + (k >> 6) * nar) << 10) + ((n & 7) << 7)
                      + ((((k & 63) << 1)) ^ ((n & 7) << 4)));
}

// ================= prep: fold + fp16 + swizzle weights =================
__global__ void prep_kernel(const float* __restrict__ W0, const float* __restrict__ W1) {
    int gid = blockIdx.x * blockDim.x + threadIdx.x;
    if (gid < 16384) {                 // B1: n=h, k=f -> Wcat[f][h]
        int n = gid >> 7, k = gid & 127;
        float v;
        if (k < 64) v = W0[(64 + k) * NH1 + n] - W0[(192 + k) * NH1 + n];
        else        v = W0[(128 + (k - 64)) * NH1 + n];
        *(__half*)((char*)&g_B1[0] + boffB(n, k, 16)) = __float2half_rn(v);
    } else if (gid < 24576) {          // B2: n=j, k=h -> W1[h][j]
        int i = gid - 16384;
        int n = i >> 7, k = i & 127;
        *(__half*)((char*)&g_B2[0] + boffB(n, k, 8)) = __float2half_rn(W1[k * NH2 + n]);
    } else if (gid < 32768) {          // Wq = W0a + W0d
        int i = gid - 24576;
        int e = i >> 7, hh = i & 127;
        g_Wq[e * NH1 + hh] = W0[e * NH1 + hh] + W0[(192 + e) * NH1 + hh];
    }
}

// ====== persistent fused kernel: 896 threads, m32 warp tiles, 2 batches/iter ======
__global__ __launch_bounds__(NTHREADS, 1)
void din_kernel(const float* __restrict__ q_g,
                const float* __restrict__ keys_g,
                const int*   __restrict__ klen_g,
                const float* __restrict__ b0_g,
                const float* __restrict__ b1_g,
                const float* __restrict__ W2_g,
                const float* __restrict__ b2_g,
                float* __restrict__ out_g,
                float* __restrict__ attn_g,
                int npairs) {
    extern __shared__ char smem[];
    const uint32_t sbase = smem_u32(smem);
    float* sW2    = (float*)(smem + OFF_W2);
    float* sB1b   = (float*)(smem + OFF_B1B);
    float* sC     = (float*)(smem + OFF_C);
    float* sScore = (float*)(smem + OFF_SCORE);
    float* sPart  = (float*)(smem + OFF_PART);
    float* sPOut  = (float*)(smem + OFF_POUT);

    const int t = threadIdx.x;
    const int lane = t & 31, w = t >> 5;
    const float b2v = b2_g[0];

    // ---- weights -> smem ONCE ----
    {
        uint4* d1 = (uint4*)(smem + OFF_B1);
        for (int i = t; i < 2048; i += NTHREADS) d1[i] = g_B1[i];
        uint4* d2 = (uint4*)(smem + OFF_B2);
        for (int i = t; i < 1024; i += NTHREADS) d2[i] = g_B2[i];
        if (t < 64) { sW2[t] = W2_g[t]; sB1b[t] = b1_g[t]; }
    }
    // zero pad rows 200..223, once
    for (int i = t; i < 24 * 64; i += NTHREADS) {
        int r = i >> 6, kk = (i & 63) * 2;
        *(uint32_t*)(smem + OFF_A + boffA(200 + r, kk)) = 0u;
    }
    __syncthreads();

    // ---- lane geometry: 7 m-groups (m32) x 4 n-groups ----
    const int mg = w >> 2, ng = w & 3;
    const int s0 = mg * 32;                    // warp row base (0..192)
    const int rA = s0 + (lane & 15);
    const uint32_t aBase = sbase + OFF_A + ((rA >> 3) << 10) + ((rA & 7) << 7);
    const uint32_t hsxA = (((lane >> 4) & 1) * 16) ^ ((lane & 7) << 4);
    const uint32_t hsxB = (((lane >> 3) & 1) * 16) ^ ((lane & 7) << 4);
    const int h0 = ng * 32;                    // GEMM1 n-range (32 wide)
    const int j0 = ng * 16;                    // GEMM2 n-range (16 wide)
    const uint32_t b1Base = sbase + OFF_B1 + (((h0 >> 3) + ((lane >> 4) & 1)) << 10)
                          + ((lane & 7) << 7);
    const uint32_t b2Base = sbase + OFF_B2 + (((j0 >> 3) + ((lane >> 4) & 1)) << 10)
                          + ((lane & 7) << 7);

    for (int p = blockIdx.x; p < npairs; p += gridDim.x) {
        const long gb0 = (long)p * 2;

        // ---- build Kp: batch0 -> rows 0..99, batch1 -> rows 100..199 ----
        for (int i = t; i < 3200; i += NTHREADS) {
            int batch = (i >= 1600), rem = i - batch * 1600;
            int s = rem >> 4, q = rem & 15;
            int row = batch * 100 + s;
            float4 kv = *(const float4*)&keys_g[((gb0 + batch) * NS + s) * NE + 4 * q];
            float4 qv = *(const float4*)&q_g[(gb0 + batch) * NE + 4 * q];
            uint2 w0;
            w0.x = cvt_f16x2(kv.x, kv.y);
            w0.y = cvt_f16x2(kv.z, kv.w);
            *(uint2*)(smem + OFF_A + boffA(row, 4 * q)) = w0;
            uint2 w1;
            w1.x = cvt_f16x2(kv.x * qv.x, kv.y * qv.y);
            w1.y = cvt_f16x2(kv.z * qv.z, kv.w * qv.w);
            *(uint2*)(smem + OFF_A + boffA(row, 64 + 4 * q)) = w1;
        }
        // ---- c[batch][h] = b0[h] + q . Wq[:,h] ----
        if (t < 256) {
            int batch = t >> 7, h = t & 127;
            const float* qb = q_g + (gb0 + batch) * NE;
            float acc0 = b0_g[h];
            #pragma unroll 8
            for (int e = 0; e < NE; e++) acc0 = fmaf(qb[e], g_Wq[e * NH1 + h], acc0);
            sC[t] = acc0;
        }
        __syncthreads();

        // ================= GEMM1: D1[224 x 128] = Kp @ Wcat =================
        // warp tile m32 x n32, single fp16 plane
        float acc[8][4];   // [mt*4 + ntile]
        #pragma unroll
        for (int i = 0; i < 8; i++)
            #pragma unroll
            for (int j = 0; j < 4; j++) acc[i][j] = 0.f;

        #pragma unroll
        for (int k = 0; k < 8; k++) {
            const uint32_t kbA = ((k < 4) ? k * 32u : 28672u + (k - 4) * 32u) ^ hsxA;
            const uint32_t kbB = ((k < 4) ? k * 32u : 16384u + (k - 4) * 32u) ^ hsxB;
            uint32_t ah0[4], ah1[4];
            ldsm4(ah0, aBase + kbA);
            ldsm4(ah1, aBase + 2048 + kbA);
            #pragma unroll
            for (int np = 0; np < 2; np++) {
                uint32_t bh[4];
                ldsm4(bh, b1Base + np * 2048 + kbB);
                const int nt = np * 2;
                mma_f16(acc[nt],         ah0, bh[0], bh[1]);
                mma_f16(acc[nt + 1],     ah0, bh[2], bh[3]);
                mma_f16(acc[4 + nt],     ah1, bh[0], bh[1]);
                mma_f16(acc[4 + nt + 1], ah1, bh[2], bh[3]);
            }
        }
        __syncthreads();   // all A reads done

        // ---- epilogue1: H0 = relu(D1 + c) -> fp16 -> A region ----
        #pragma unroll
        for (int mt = 0; mt < 2; mt++) {
            const int row = s0 + mt * 16 + (lane >> 2);
            const int cb0 = (row >= 100 ? 128 : 0);
            const int cb8 = (row + 8 >= 100 ? 128 : 0);
            #pragma unroll
            for (int nt = 0; nt < 4; nt++) {
                const float* c = acc[mt * 4 + nt];
                const int col = h0 + nt * 8 + (lane & 3) * 2;
                const float c0 = sC[cb0 + col], c1 = sC[cb0 + col + 1];
                const float d0 = sC[cb8 + col], d1 = sC[cb8 + col + 1];
                *(uint32_t*)(smem + OFF_A + boffA(row, col)) =
                    cvt_f16x2(fmaxf(c[0] + c0, 0.f), fmaxf(c[1] + c1, 0.f));
                *(uint32_t*)(smem + OFF_A + boffA(row + 8, col)) =
                    cvt_f16x2(fmaxf(c[2] + d0, 0.f), fmaxf(c[3] + d1, 0.f));
            }
        }
        __syncthreads();

        // ================= GEMM2: D2[224 x 64] = H0 @ W1 =================
        // warp tile m32 x n16, single fp16 plane
        float acc2[4][4];   // [mt*2 + nhalf]
        #pragma unroll
        for (int i = 0; i < 4; i++)
            #pragma unroll
            for (int j = 0; j < 4; j++) acc2[i][j] = 0.f;

        #pragma unroll
        for (int k = 0; k < 8; k++) {
            const uint32_t kbA = ((k < 4) ? k * 32u : 28672u + (k - 4) * 32u) ^ hsxA;
            const uint32_t kbB = ((k < 4) ? k * 32u : 8192u + (k - 4) * 32u) ^ hsxB;
            uint32_t ah0[4], ah1[4];
            ldsm4(ah0, aBase + kbA);
            ldsm4(ah1, aBase + 2048 + kbA);
            uint32_t bh[4];
            ldsm4(bh, b2Base + kbB);
            mma_f16(acc2[0], ah0, bh[0], bh[1]);
            mma_f16(acc2[1], ah0, bh[2], bh[3]);
            mma_f16(acc2[2], ah1, bh[0], bh[1]);
            mma_f16(acc2[3], ah1, bh[2], bh[3]);
        }

        // ---- epilogue2: partial scores -> sPart[row][ng] ----
        {
            float part[4] = {0.f, 0.f, 0.f, 0.f};   // [mt*2 + rowhalf]
            #pragma unroll
            for (int mt = 0; mt < 2; mt++) {
                #pragma unroll
                for (int nt = 0; nt < 2; nt++) {
                    const float* c = acc2[mt * 2 + nt];
                    const int col = j0 + nt * 8 + (lane & 3) * 2;
                    const float bb0 = sB1b[col], bb1 = sB1b[col + 1];
                    const float w0v = sW2[col], w1v = sW2[col + 1];
                    part[mt * 2]     += fmaxf(c[0] + bb0, 0.f) * w0v + fmaxf(c[1] + bb1, 0.f) * w1v;
                    part[mt * 2 + 1] += fmaxf(c[2] + bb0, 0.f) * w0v + fmaxf(c[3] + bb1, 0.f) * w1v;
                }
            }
            #pragma unroll
            for (int i = 0; i < 4; i++) {
                float v = part[i];
                v += __shfl_xor_sync(0xffffffffu, v, 1);
                v += __shfl_xor_sync(0xffffffffu, v, 2);
                if ((lane & 3) == 0) {
                    const int row = s0 + (i >> 1) * 16 + (lane >> 2) + (i & 1) * 8;
                    sPart[row * 4 + ng] = v;
                }
            }
        }
        __syncthreads();

        // ---- masked softmax + attn store: warp 0 -> batch0, warp 1 -> batch1 ----
        if (t < 64) {
            const int batch = t >> 5;
            float* sc = sScore + batch * 128;
            const float* pp = sPart + batch * 100 * 4;
            const int len = klen_g[gb0 + batch];
            float m = -1e30f;
            float sv[4];
            #pragma unroll
            for (int i = 0; i < 4; i++) {
                int s = lane + i * 32;
                float v = -1e30f;
                if (s < NS) {
                    v = pp[s * 4] + pp[s * 4 + 1] + pp[s * 4 + 2] + pp[s * 4 + 3] + b2v;
                    if (s >= len) v = -1e30f;
                }
                sv[i] = v;
                m = fmaxf(m, v);
            }
            #pragma unroll
            for (int off = 16; off; off >>= 1)
                m = fmaxf(m, __shfl_xor_sync(0xffffffffu, m, off));
            float sum = 0.f;
            #pragma unroll
            for (int i = 0; i < 4; i++) {
                int s = lane + i * 32;
                float v = (s < len) ? expf(sv[i] - m) : 0.f;
                sv[i] = v;
                sum += v;
            }
            #pragma unroll
            for (int off = 16; off; off >>= 1)
                sum += __shfl_xor_sync(0xffffffffu, sum, off);
            float inv = 1.f / sum;
            #pragma unroll
            for (int i = 0; i < 4; i++) {
                int s = lane + i * 32;
                if (s < NS) {
                    float a = sv[i] * inv;
                    sc[s] = a;
                    if (attn_g) attn_g[(gb0 + batch) * NS + s] = a;
                }
            }
        }
        __syncthreads();

        // ---- out[e] = sum_s attn[s] * keys[s][e] ----
        if (t < 256) {
            const int batch = t >> 7, rem = t & 127, g = rem >> 6, e = rem & 63;
            const float* kb = keys_g + (gb0 + batch) * NS * NE;
            const float* sc = sScore + batch * 128;
            float a = 0.f;
            for (int s = g; s < NS; s += 2) a = fmaf(sc[s], kb[s * NE + e], a);
            sPOut[batch * 128 + g * 64 + e] = a;
        }
        __syncthreads();
        if (t < 128) {
            const int batch = t >> 6, e = t & 63;
            out_g[(gb0 + batch) * NE + e] = sPOut[batch * 128 + e] + sPOut[batch * 128 + 64 + e];
        }
        // next iteration's first smem writes (A/sC) are separated from all
        // remaining readers by the barrier chain above.
    }
}

extern "C" void kernel_launch(void* const* d_in, const int* in_sizes, int n_in,
                              void* d_out, int out_size) {
    const float* query = (const float*)d_in[0];
    const float* keys  = (const float*)d_in[1];
    const int*   klen  = (const int*)  d_in[2];
    const float* W0    = (const float*)d_in[3];
    const float* b0    = (const float*)d_in[4];
    const float* W1    = (const float*)d_in[5];
    const float* b1    = (const float*)d_in[6];
    const float* W2    = (const float*)d_in[7];
    const float* b2    = (const float*)d_in[8];

    float* outp  = (float*)d_out;
    float* attnp = (out_size >= NB * NE + NB * NS) ? outp + (size_t)NB * NE : nullptr;

    int dev = 0, nsm = 148;
    cudaGetDevice(&dev);
    cudaDeviceGetAttribute(&nsm, cudaDevAttrMultiProcessorCount, dev);

    cudaFuncSetAttribute(din_kernel, cudaFuncAttributeMaxDynamicSharedMemorySize, SMEM_TOTAL);

    prep_kernel<<<64, 512>>>(W0, W1);
    din_kernel<<<nsm, NTHREADS, SMEM_TOTAL>>>(query, keys, klen, b0, b1, W2, b2,
                                              outp, attnp, NB / 2);
}